// round 2
// baseline (speedup 1.0000x reference)
#include <cuda_runtime.h>
#include <cuda_bf16.h>

// Problem constants
#define TPAD  65656      // t_padded = T_SIM + T_KERNEL - 1
#define TOUT  65536      // output time samples
#define CCH   384        // channels
#define NROWS 768        // SIZE * C
#define NB    168        // number of OA blocks = ceil(TPAD / HOP)
#define HOP   392        // BLOCK - s2 + 1
#define S2    121        // kernel length
#define NFFT  512        // OA block size

// 201 MB scratch for filtered signal y[row][t], row = n*384 + c
__device__ float g_y[(size_t)NROWS * TOUT];

// ---------------------------------------------------------------------------
// Kernel 0: zero the scratch (needed because overlap strips use atomicAdd)
// ---------------------------------------------------------------------------
__global__ void zero_kernel() {
    size_t i = (size_t)blockIdx.x * blockDim.x + threadIdx.x;
    size_t n4 = (size_t)NROWS * TOUT / 4;
    float4* p = reinterpret_cast<float4*>(g_y);
    float4 z = make_float4(0.f, 0.f, 0.f, 0.f);
    for (size_t k = i; k < n4; k += (size_t)gridDim.x * blockDim.x) p[k] = z;
}

// ---------------------------------------------------------------------------
// Kernel 1: per-(row-pair, block) overlap-add FFT convolution.
// Two real rows are packed into one complex signal; since the frequency
// multiplier is real & conjugate-symmetric, filtering commutes with packing:
//   ifft(fft(x0 + i*x1) * Kext) = conv(x0,h) + i*conv(x1,h).
// ortho norms of rfft/irfft cancel -> plain circular conv (ifft has 1/512).
// ---------------------------------------------------------------------------
__device__ __forceinline__ float2 cmul(float2 a, float2 b) {
    return make_float2(fmaf(a.x, b.x, -a.y * b.y), fmaf(a.x, b.y, a.y * b.x));
}

__global__ __launch_bounds__(128) void conv_kernel(
    const float* __restrict__ noise, const float* __restrict__ kf)
{
    __shared__ float2 bufA[NFFT];
    __shared__ float2 bufB[NFFT];
    __shared__ float2 tw[256];     // tw[j] = exp(-i*2*pi*j/512)
    __shared__ float  ks[257];

    const int tid = threadIdx.x;          // 128 threads
    const int b   = blockIdx.x;           // OA block index
    const int q   = blockIdx.y;           // row pair index
    const int row0 = 2 * q, row1 = 2 * q + 1;
    const int base = b * HOP;

    // twiddle table (accurate sincospi)
    #pragma unroll
    for (int h = 0; h < 2; h++) {
        int j = tid + 128 * h;
        float s, c;
        sincospif(-(float)j * (1.0f / 256.0f), &s, &c);
        tw[j] = make_float2(c, s);
    }
    for (int i = tid; i < 257; i += 128) ks[i] = kf[i];

    // load input block: 392 samples (bounds-checked), zero-pad to 512
    const float* n0 = noise + (size_t)row0 * TPAD;
    const float* n1 = noise + (size_t)row1 * TPAD;
    #pragma unroll
    for (int h = 0; h < 4; h++) {
        int i = tid + 128 * h;
        float v0 = 0.f, v1 = 0.f;
        int p = base + i;
        if (i < HOP && p < TPAD) { v0 = n0[p]; v1 = n1[p]; }
        bufA[i] = make_float2(v0, v1);
    }
    __syncthreads();

    // ---- forward FFT (Stockham autosort, radix-2, 9 stages) ----
    float2* src = bufA;
    float2* dst = bufB;
    #pragma unroll
    for (int s = 0; s < 9; s++) {
        const int m = 1 << s;
        #pragma unroll
        for (int h = 0; h < 2; h++) {
            int idx = tid + 128 * h;          // 0..255
            int jm  = idx & ~(m - 1);
            float2 c0 = src[idx];
            float2 c1 = src[idx + 256];
            float2 w  = tw[jm];
            float2 sum = make_float2(c0.x + c1.x, c0.y + c1.y);
            float2 dif = make_float2(c0.x - c1.x, c0.y - c1.y);
            dst[idx + jm]     = sum;
            dst[idx + jm + m] = cmul(w, dif);
        }
        float2* t = src; src = dst; dst = t;
        __syncthreads();
    }
    // result now in src (= bufB)

    // ---- spectrum multiply by real symmetric extension of kernel_fft ----
    #pragma unroll
    for (int h = 0; h < 4; h++) {
        int k  = tid + 128 * h;
        int kk = (k <= 256) ? k : (NFFT - k);
        float sc = ks[kk];
        float2 v = src[k];
        src[k] = make_float2(v.x * sc, v.y * sc);
    }
    __syncthreads();

    // ---- inverse FFT (conjugate twiddles), result picks up 1/512 at write ----
    #pragma unroll
    for (int s = 0; s < 9; s++) {
        const int m = 1 << s;
        #pragma unroll
        for (int h = 0; h < 2; h++) {
            int idx = tid + 128 * h;
            int jm  = idx & ~(m - 1);
            float2 c0 = src[idx];
            float2 c1 = src[idx + 256];
            float2 w  = tw[jm];
            w.y = -w.y;
            float2 sum = make_float2(c0.x + c1.x, c0.y + c1.y);
            float2 dif = make_float2(c0.x - c1.x, c0.y - c1.y);
            dst[idx + jm]     = sum;
            dst[idx + jm + m] = cmul(w, dif);
        }
        float2* t = src; src = dst; dst = t;
        __syncthreads();
    }
    // result now in src (= bufA)

    // ---- overlap-add write-out with global slice offset s2-1 = 120 ----
    const float inv = 1.0f / (float)NFFT;
    float* y0 = g_y + (size_t)row0 * TOUT;
    float* y1 = g_y + (size_t)row1 * TOUT;
    #pragma unroll
    for (int h = 0; h < 4; h++) {
        int j = tid + 128 * h;
        int t = base + j - (S2 - 1);
        if (t < 0 || t >= TOUT) continue;
        float2 v = src[j];
        float v0 = v.x * inv, v1 = v.y * inv;
        if (j >= (S2 - 1) && j < HOP) {       // exclusive region: plain store
            y0[t] = v0;
            y1[t] = v1;
        } else {                              // 120-sample overlap strips
            atomicAdd(&y0[t], v0);
            atomicAdd(&y1[t], v1);
        }
    }
}

// ---------------------------------------------------------------------------
// Kernel 2: Y[n,t,d] = sum_c g_y[n*384+c][t] * (std[c]*vt[c,d])
// fp32 tiled GEMM: BM=128 (t), BN=128 (d), BK=16, 256 threads, 8x8 micro.
// All tile counts divide exactly -> no bounds checks.
// ---------------------------------------------------------------------------
#define BM 128
#define BN 128
#define BK 16

__global__ __launch_bounds__(256, 2) void gemm_kernel(
    const float* __restrict__ vt, const float* __restrict__ stdv,
    float* __restrict__ out)
{
    __shared__ float As[2][BK][BM];
    __shared__ float Bs[2][BK][BN];

    const int tid = threadIdx.x;
    const int bx = blockIdx.x;      // t tile  (512)
    const int by = blockIdx.y;      // d tile  (3)
    const int z  = blockIdx.z;      // n       (2)
    const int t0 = bx * BM, d0 = by * BN;

    const float* Ab = g_y + (size_t)z * CCH * TOUT + (size_t)t0;
    const float* Bb = vt + d0;

    const int tx = tid & 15, ty = tid >> 4;

    // global->smem mapping: 2048 floats per tile = 512 float4 = 2 per thread
    const int f0 = tid, f1 = tid + 256;
    const int ka0 = f0 >> 5, ca0 = (f0 & 31) * 4;
    const int ka1 = f1 >> 5, ca1 = (f1 & 31) * 4;

    float acc[8][8] = {};

    // preload tile 0
    {
        *(float4*)&As[0][ka0][ca0] = *(const float4*)(Ab + (size_t)ka0 * TOUT + ca0);
        *(float4*)&As[0][ka1][ca1] = *(const float4*)(Ab + (size_t)ka1 * TOUT + ca1);
        float s0 = stdv[ka0], s1 = stdv[ka1];
        float4 b0 = *(const float4*)(Bb + (size_t)ka0 * CCH + ca0);
        float4 b1 = *(const float4*)(Bb + (size_t)ka1 * CCH + ca1);
        b0.x *= s0; b0.y *= s0; b0.z *= s0; b0.w *= s0;
        b1.x *= s1; b1.y *= s1; b1.z *= s1; b1.w *= s1;
        *(float4*)&Bs[0][ka0][ca0] = b0;
        *(float4*)&Bs[0][ka1][ca1] = b1;
    }
    __syncthreads();

    const int KT = CCH / BK;   // 24
    for (int kt = 0; kt < KT; kt++) {
        const int cur = kt & 1, nxt = cur ^ 1;
        float4 pa0, pa1, pb0, pb1;
        const bool more = (kt + 1 < KT);
        if (more) {
            int kk0 = (kt + 1) * BK + ka0;
            int kk1 = (kt + 1) * BK + ka1;
            pa0 = *(const float4*)(Ab + (size_t)kk0 * TOUT + ca0);
            pa1 = *(const float4*)(Ab + (size_t)kk1 * TOUT + ca1);
            float s0 = stdv[kk0], s1 = stdv[kk1];
            pb0 = *(const float4*)(Bb + (size_t)kk0 * CCH + ca0);
            pb1 = *(const float4*)(Bb + (size_t)kk1 * CCH + ca1);
            pb0.x *= s0; pb0.y *= s0; pb0.z *= s0; pb0.w *= s0;
            pb1.x *= s1; pb1.y *= s1; pb1.z *= s1; pb1.w *= s1;
        }
        #pragma unroll
        for (int k = 0; k < BK; k++) {
            float a[8], bb[8];
            *(float4*)&a[0]  = *(const float4*)&As[cur][k][ty * 8];
            *(float4*)&a[4]  = *(const float4*)&As[cur][k][ty * 8 + 4];
            *(float4*)&bb[0] = *(const float4*)&Bs[cur][k][tx * 8];
            *(float4*)&bb[4] = *(const float4*)&Bs[cur][k][tx * 8 + 4];
            #pragma unroll
            for (int i = 0; i < 8; i++)
                #pragma unroll
                for (int j = 0; j < 8; j++)
                    acc[i][j] = fmaf(a[i], bb[j], acc[i][j]);
        }
        if (more) {
            *(float4*)&As[nxt][ka0][ca0] = pa0;
            *(float4*)&As[nxt][ka1][ca1] = pa1;
            *(float4*)&Bs[nxt][ka0][ca0] = pb0;
            *(float4*)&Bs[nxt][ka1][ca1] = pb1;
        }
        __syncthreads();
    }

    // epilogue: out[(z*TOUT + t)*CCH + d]
    float* ob = out + ((size_t)z * TOUT + t0) * CCH + d0;
    #pragma unroll
    for (int i = 0; i < 8; i++) {
        int t = ty * 8 + i;
        float* op = ob + (size_t)t * CCH + tx * 8;
        *(float4*)op       = make_float4(acc[i][0], acc[i][1], acc[i][2], acc[i][3]);
        *(float4*)(op + 4) = make_float4(acc[i][4], acc[i][5], acc[i][6], acc[i][7]);
    }
}

// ---------------------------------------------------------------------------
extern "C" void kernel_launch(void* const* d_in, const int* in_sizes, int n_in,
                              void* d_out, int out_size)
{
    const float* noise = (const float*)d_in[0];   // (768, 65656)
    const float* stdv  = (const float*)d_in[1];   // (384,)
    const float* vt    = (const float*)d_in[2];   // (384, 384)
    const float* kf    = (const float*)d_in[3];   // (257,)
    // d_in[4] = s2 (compile-time constant 121)

    zero_kernel<<<1184, 256>>>();
    conv_kernel<<<dim3(NB, NROWS / 2), 128>>>(noise, kf);
    gemm_kernel<<<dim3(TOUT / BM, CCH / BN, 2), 256>>>(vt, stdv, (float*)d_out);
}

// round 3
// speedup vs baseline: 1.9133x; 1.9133x over previous
#include <cuda_runtime.h>
#include <cuda_bf16.h>
#include <cstdint>

// Problem constants
#define TPAD  65656      // t_padded = T_SIM + T_KERNEL - 1
#define TOUT  65536      // output time samples
#define CCH   384        // channels
#define NROWS 768        // SIZE * C
#define NB    168        // number of OA blocks
#define HOP   392        // BLOCK - s2 + 1
#define S2    121        // kernel length
#define NFFT  512        // OA block size

// Scratch: filtered signal y[row][t] (fp32), row = n*384 + c   (201 MB)
__device__ float g_y[(size_t)NROWS * TOUT];
// Precomputed W[d][c] = std[c]*vt[c][d], split into bf16 hi/lo
__device__ __nv_bfloat16 g_Whi[CCH * CCH];
__device__ __nv_bfloat16 g_Wlo[CCH * CCH];

// ---------------------------------------------------------------------------
// prep_w: W[d][c] = std[c]*vt[c][d] -> bf16 hi + bf16 lo (error compensation)
// ---------------------------------------------------------------------------
__global__ void prep_w(const float* __restrict__ vt, const float* __restrict__ stdv) {
    int i = blockIdx.x * 256 + threadIdx.x;
    if (i < CCH * CCH) {
        int d = i / CCH, c = i % CCH;
        float w = stdv[c] * vt[c * CCH + d];
        __nv_bfloat16 hi = __float2bfloat16(w);
        g_Whi[i] = hi;
        g_Wlo[i] = __float2bfloat16(w - __bfloat162float(hi));
    }
}

// ---------------------------------------------------------------------------
// zero_strips: only the 120-sample overlap strips receive atomicAdd, so only
// those need pre-zeroing. Strip b covers t in [392b+272, 392b+392), b=0..166.
// ---------------------------------------------------------------------------
__global__ void zero_strips() {
    int b = blockIdx.x;            // 0..166
    int r = blockIdx.y;            // 0..767
    int t0 = b * HOP + 272;        // 16B-aligned (1088+1568b bytes)
    float4* p = reinterpret_cast<float4*>(g_y + (size_t)r * TOUT + t0);
    if (threadIdx.x < 30) p[threadIdx.x] = make_float4(0.f, 0.f, 0.f, 0.f);
}

// ---------------------------------------------------------------------------
// conv_kernel: per-(row-pair, block) overlap-add FFT convolution (unchanged).
// Two real rows packed into one complex signal (real symmetric multiplier).
// ---------------------------------------------------------------------------
__device__ __forceinline__ float2 cmul(float2 a, float2 b) {
    return make_float2(fmaf(a.x, b.x, -a.y * b.y), fmaf(a.x, b.y, a.y * b.x));
}

__global__ __launch_bounds__(128) void conv_kernel(
    const float* __restrict__ noise, const float* __restrict__ kf)
{
    __shared__ float2 bufA[NFFT];
    __shared__ float2 bufB[NFFT];
    __shared__ float2 tw[256];
    __shared__ float  ks[257];

    const int tid = threadIdx.x;
    const int b   = blockIdx.x;
    const int q   = blockIdx.y;
    const int row0 = 2 * q, row1 = 2 * q + 1;
    const int base = b * HOP;

    #pragma unroll
    for (int h = 0; h < 2; h++) {
        int j = tid + 128 * h;
        float s, c;
        sincospif(-(float)j * (1.0f / 256.0f), &s, &c);
        tw[j] = make_float2(c, s);
    }
    for (int i = tid; i < 257; i += 128) ks[i] = kf[i];

    const float* n0 = noise + (size_t)row0 * TPAD;
    const float* n1 = noise + (size_t)row1 * TPAD;
    #pragma unroll
    for (int h = 0; h < 4; h++) {
        int i = tid + 128 * h;
        float v0 = 0.f, v1 = 0.f;
        int p = base + i;
        if (i < HOP && p < TPAD) { v0 = n0[p]; v1 = n1[p]; }
        bufA[i] = make_float2(v0, v1);
    }
    __syncthreads();

    float2* src = bufA;
    float2* dst = bufB;
    #pragma unroll
    for (int s = 0; s < 9; s++) {
        const int m = 1 << s;
        #pragma unroll
        for (int h = 0; h < 2; h++) {
            int idx = tid + 128 * h;
            int jm  = idx & ~(m - 1);
            float2 c0 = src[idx];
            float2 c1 = src[idx + 256];
            float2 w  = tw[jm];
            float2 sum = make_float2(c0.x + c1.x, c0.y + c1.y);
            float2 dif = make_float2(c0.x - c1.x, c0.y - c1.y);
            dst[idx + jm]     = sum;
            dst[idx + jm + m] = cmul(w, dif);
        }
        float2* t = src; src = dst; dst = t;
        __syncthreads();
    }

    #pragma unroll
    for (int h = 0; h < 4; h++) {
        int k  = tid + 128 * h;
        int kk = (k <= 256) ? k : (NFFT - k);
        float sc = ks[kk];
        float2 v = src[k];
        src[k] = make_float2(v.x * sc, v.y * sc);
    }
    __syncthreads();

    #pragma unroll
    for (int s = 0; s < 9; s++) {
        const int m = 1 << s;
        #pragma unroll
        for (int h = 0; h < 2; h++) {
            int idx = tid + 128 * h;
            int jm  = idx & ~(m - 1);
            float2 c0 = src[idx];
            float2 c1 = src[idx + 256];
            float2 w  = tw[jm];
            w.y = -w.y;
            float2 sum = make_float2(c0.x + c1.x, c0.y + c1.y);
            float2 dif = make_float2(c0.x - c1.x, c0.y - c1.y);
            dst[idx + jm]     = sum;
            dst[idx + jm + m] = cmul(w, dif);
        }
        float2* t = src; src = dst; dst = t;
        __syncthreads();
    }

    const float inv = 1.0f / (float)NFFT;
    float* y0 = g_y + (size_t)row0 * TOUT;
    float* y1 = g_y + (size_t)row1 * TOUT;
    #pragma unroll
    for (int h = 0; h < 4; h++) {
        int j = tid + 128 * h;
        int t = base + j - (S2 - 1);
        if (t < 0 || t >= TOUT) continue;
        float2 v = src[j];
        float v0 = v.x * inv, v1 = v.y * inv;
        if (j >= (S2 - 1) && j < HOP) {
            y0[t] = v0;
            y1[t] = v1;
        } else {
            atomicAdd(&y0[t], v0);
            atomicAdd(&y1[t], v1);
        }
    }
}

// ---------------------------------------------------------------------------
// Tensor-core GEMM with 3-term bf16 split:
//   C[t][d] = sum_c y[c][t] * W[d][c],   K' = 3*384 (passes: hi*hi, lo*hi, hi*lo)
// A = y (M=t, K=c), stored K-major in smem [k][m] -> ldmatrix .trans
// B = W (N=d, K=c), stored [n][k]               -> ldmatrix non-trans
// ---------------------------------------------------------------------------
#define BM 128
#define BN 128
#define BK 32
#define ASTRIDE (BM + 8)        // 136 bf16
#define BSTRIDE (BK + 8)        // 40 bf16
#define ABUF (BK * ASTRIDE)     // 4352 elems per stage
#define BBUF (BN * BSTRIDE)     // 5120 elems per stage

__device__ __forceinline__ uint32_t smem_u32(const void* p) {
    return (uint32_t)__cvta_generic_to_shared(p);
}
__device__ __forceinline__ void ldmT4(uint32_t* r, uint32_t addr) {
    asm volatile("ldmatrix.sync.aligned.m8n8.x4.trans.shared.b16 {%0,%1,%2,%3},[%4];\n"
                 : "=r"(r[0]), "=r"(r[1]), "=r"(r[2]), "=r"(r[3]) : "r"(addr));
}
__device__ __forceinline__ void ldmN4(uint32_t* r, uint32_t addr) {
    asm volatile("ldmatrix.sync.aligned.m8n8.x4.shared.b16 {%0,%1,%2,%3},[%4];\n"
                 : "=r"(r[0]), "=r"(r[1]), "=r"(r[2]), "=r"(r[3]) : "r"(addr));
}
__device__ __forceinline__ void mma16816(float* c, const uint32_t* a, const uint32_t* b) {
    asm volatile("mma.sync.aligned.m16n8k16.row.col.f32.bf16.bf16.f32 "
                 "{%0,%1,%2,%3},{%4,%5,%6,%7},{%8,%9},{%0,%1,%2,%3};\n"
                 : "+f"(c[0]), "+f"(c[1]), "+f"(c[2]), "+f"(c[3])
                 : "r"(a[0]), "r"(a[1]), "r"(a[2]), "r"(a[3]), "r"(b[0]), "r"(b[1]));
}
__device__ __forceinline__ uint32_t pack_bf16(float x, float y) {
    __nv_bfloat162 h = __floats2bfloat162_rn(x, y);
    return *reinterpret_cast<uint32_t*>(&h);
}
__device__ __forceinline__ uint32_t pack_bf16_lo(float x, float y) {
    float hx = __bfloat162float(__float2bfloat16(x));
    float hy = __bfloat162float(__float2bfloat16(y));
    return pack_bf16(x - hx, y - hy);
}

__global__ __launch_bounds__(256, 1) void gemm_bf16(float* __restrict__ out) {
    __shared__ __align__(16) __nv_bfloat16 As[2 * ABUF];
    __shared__ __align__(16) __nv_bfloat16 Bs[2 * BBUF];

    const int tid  = threadIdx.x;
    const int lane = tid & 31;
    const int w    = tid >> 5;
    const int wm   = w & 1;        // m-half (64)
    const int wn   = w >> 1;       // n-quarter (32)

    const int d0 = blockIdx.x * BN;    // 0..2
    const int t0 = blockIdx.y * BM;    // 0..511
    const int z  = blockIdx.z;         // 0..1

    const float* Ag = g_y + (size_t)z * CCH * TOUT + t0;

    // A loader: 1024 float4 / 256 thr = 4 each
    const int akr = tid >> 5;             // +8 per i
    const int am4 = (tid & 31) << 2;
    // B loader: 512 uint4 / 256 thr = 2 each
    const int bnr = tid >> 2;             // +64 per i
    const int bkc = (tid & 3) << 3;

    // ldmatrix per-lane offsets
    const int g  = lane >> 3, r = lane & 7;
    const int ak = ((g & 2) << 2) + r;    // k row (+8 for g>=2)
    const int amo = (g & 1) << 3;         // m +8 for odd g
    const int bn = ((g & 2) << 2) + r;
    const int bko = (g & 1) << 3;

    const uint32_t as0 = smem_u32(As);
    const uint32_t bs0 = smem_u32(Bs);
    uint32_t aAddr[4], bAddr[2];
    #pragma unroll
    for (int mi = 0; mi < 4; mi++)
        aAddr[mi] = as0 + (uint32_t)((ak * ASTRIDE + wm * 64 + mi * 16 + amo) * 2);
    #pragma unroll
    for (int nj = 0; nj < 2; nj++)
        bAddr[nj] = bs0 + (uint32_t)(((wn * 32 + nj * 16 + bn) * BSTRIDE + bko) * 2);

    float acc[4][4][4];
    #pragma unroll
    for (int i = 0; i < 4; i++)
        #pragma unroll
        for (int j = 0; j < 4; j++)
            #pragma unroll
            for (int k = 0; k < 4; k++) acc[i][j][k] = 0.f;

    const int NKT = 36;     // K' = 1152 / BK
    float4 va[4];
    uint4  vb[2];

    // ---- load chunk 0 ----
    {
        const float* Ap = Ag;                       // ksrc0 = 0
        #pragma unroll
        for (int i = 0; i < 4; i++)
            va[i] = *(const float4*)(Ap + (size_t)(akr + 8 * i) * TOUT + am4);
        const __nv_bfloat16* Wp = g_Whi + (size_t)d0 * CCH;
        #pragma unroll
        for (int i = 0; i < 2; i++)
            vb[i] = *(const uint4*)(Wp + (size_t)(bnr + 64 * i) * CCH + bkc);
        #pragma unroll
        for (int i = 0; i < 4; i++) {
            uint2 s;
            s.x = pack_bf16(va[i].x, va[i].y);
            s.y = pack_bf16(va[i].z, va[i].w);
            *(uint2*)&As[(akr + 8 * i) * ASTRIDE + am4] = s;
        }
        #pragma unroll
        for (int i = 0; i < 2; i++)
            *(uint4*)&Bs[(bnr + 64 * i) * BSTRIDE + bkc] = vb[i];
    }
    __syncthreads();

    for (int kt = 0; kt < NKT; kt++) {
        const int buf = kt & 1;
        const bool more = (kt + 1 < NKT);
        int pn = 0, lo_mode = 0;
        if (more) {
            const int ktn = kt + 1;
            pn = ktn / 12;                      // pass: 0 hi*hi, 1 lo*hi, 2 hi*lo
            lo_mode = (pn == 1);
            const int ksrc0 = (ktn - pn * 12) * 32;
            const float* Ap = Ag + (size_t)ksrc0 * TOUT;
            #pragma unroll
            for (int i = 0; i < 4; i++)
                va[i] = *(const float4*)(Ap + (size_t)(akr + 8 * i) * TOUT + am4);
            const __nv_bfloat16* Wp = (pn == 2 ? g_Wlo : g_Whi) + (size_t)d0 * CCH + ksrc0;
            #pragma unroll
            for (int i = 0; i < 2; i++)
                vb[i] = *(const uint4*)(Wp + (size_t)(bnr + 64 * i) * CCH + bkc);
        }

        // ---- compute on buf ----
        const uint32_t aob = buf ? (uint32_t)(ABUF * 2) : 0u;
        const uint32_t bob = buf ? (uint32_t)(BBUF * 2) : 0u;
        #pragma unroll
        for (int kh = 0; kh < 2; kh++) {
            uint32_t afr[4][4], bfr[2][4];
            #pragma unroll
            for (int mi = 0; mi < 4; mi++)
                ldmT4(afr[mi], aAddr[mi] + aob + (uint32_t)(kh * 16 * ASTRIDE * 2));
            #pragma unroll
            for (int nj = 0; nj < 2; nj++)
                ldmN4(bfr[nj], bAddr[nj] + bob + (uint32_t)(kh * 32));
            #pragma unroll
            for (int mi = 0; mi < 4; mi++)
                #pragma unroll
                for (int n8 = 0; n8 < 4; n8++)
                    mma16816(acc[mi][n8], afr[mi], &bfr[n8 >> 1][(n8 & 1) * 2]);
        }

        // ---- stage chunk kt+1 into buf^1 ----
        if (more) {
            const int nb = buf ^ 1;
            __nv_bfloat16* Asn = As + nb * ABUF;
            __nv_bfloat16* Bsn = Bs + nb * BBUF;
            if (lo_mode) {
                #pragma unroll
                for (int i = 0; i < 4; i++) {
                    uint2 s;
                    s.x = pack_bf16_lo(va[i].x, va[i].y);
                    s.y = pack_bf16_lo(va[i].z, va[i].w);
                    *(uint2*)&Asn[(akr + 8 * i) * ASTRIDE + am4] = s;
                }
            } else {
                #pragma unroll
                for (int i = 0; i < 4; i++) {
                    uint2 s;
                    s.x = pack_bf16(va[i].x, va[i].y);
                    s.y = pack_bf16(va[i].z, va[i].w);
                    *(uint2*)&Asn[(akr + 8 * i) * ASTRIDE + am4] = s;
                }
            }
            #pragma unroll
            for (int i = 0; i < 2; i++)
                *(uint4*)&Bsn[(bnr + 64 * i) * BSTRIDE + bkc] = vb[i];
        }
        __syncthreads();
    }

    // ---- epilogue: C[t][d] ----
    const int cm  = lane >> 2;
    const int cn2 = (lane & 3) << 1;
    #pragma unroll
    for (int mi = 0; mi < 4; mi++) {
        const int t = t0 + wm * 64 + mi * 16 + cm;
        float* orow = out + ((size_t)z * TOUT + t) * CCH + d0 + wn * 32 + cn2;
        #pragma unroll
        for (int n8 = 0; n8 < 4; n8++) {
            float* o1 = orow + n8 * 8;
            *(float2*)o1             = make_float2(acc[mi][n8][0], acc[mi][n8][1]);
            *(float2*)(o1 + 8 * CCH) = make_float2(acc[mi][n8][2], acc[mi][n8][3]);
        }
    }
}

// ---------------------------------------------------------------------------
extern "C" void kernel_launch(void* const* d_in, const int* in_sizes, int n_in,
                              void* d_out, int out_size)
{
    const float* noise = (const float*)d_in[0];   // (768, 65656)
    const float* stdv  = (const float*)d_in[1];   // (384,)
    const float* vt    = (const float*)d_in[2];   // (384, 384)
    const float* kf    = (const float*)d_in[3];   // (257,)

    prep_w<<<(CCH * CCH + 255) / 256, 256>>>(vt, stdv);
    zero_strips<<<dim3(NB - 1, NROWS), 32>>>();
    conv_kernel<<<dim3(NB, NROWS / 2), 128>>>(noise, kf);
    gemm_bf16<<<dim3(CCH / BN, TOUT / BM, 2), 256>>>((float*)d_out);
}

// round 4
// speedup vs baseline: 2.4595x; 1.2855x over previous
#include <cuda_runtime.h>
#include <cuda_bf16.h>
#include <cstdint>

// Problem constants
#define TPAD  65656      // t_padded = T_SIM + T_KERNEL - 1
#define TOUT  65536      // output time samples
#define CCH   384        // channels
#define NROWS 768        // SIZE * C
#define NB    168        // number of OA blocks
#define HOP   392        // BLOCK - s2 + 1
#define S2    121        // kernel length
#define NFFT  512        // OA block size

// fp32 scratch: only the 120-sample overlap strips are summed here
__device__ float g_y[(size_t)NROWS * TOUT];
// bf16 hi/lo split of the filtered signal y[row][t]
__device__ __align__(256) __nv_bfloat16 g_yhi[(size_t)NROWS * TOUT];
__device__ __align__(256) __nv_bfloat16 g_ylo[(size_t)NROWS * TOUT];
// Precomputed W[d][c] = std[c]*vt[c][d], split into bf16 hi/lo
__device__ __align__(256) __nv_bfloat16 g_Whi[CCH * CCH];
__device__ __align__(256) __nv_bfloat16 g_Wlo[CCH * CCH];

// ---------------------------------------------------------------------------
__global__ void prep_w(const float* __restrict__ vt, const float* __restrict__ stdv) {
    int i = blockIdx.x * 256 + threadIdx.x;
    if (i < CCH * CCH) {
        int d = i / CCH, c = i % CCH;
        float w = stdv[c] * vt[c * CCH + d];
        __nv_bfloat16 hi = __float2bfloat16(w);
        g_Whi[i] = hi;
        g_Wlo[i] = __float2bfloat16(w - __bfloat162float(hi));
    }
}

// zero only the atomicAdd targets: strips t in [392b+272, 392b+392), b=0..166
__global__ void zero_strips() {
    int b = blockIdx.x;            // 0..166
    int r = blockIdx.y;            // 0..767
    int t0 = b * HOP + 272;
    float4* p = reinterpret_cast<float4*>(g_y + (size_t)r * TOUT + t0);
    if (threadIdx.x < 30) p[threadIdx.x] = make_float4(0.f, 0.f, 0.f, 0.f);
}

// after conv: convert summed fp32 strips into the bf16 hi/lo arrays
__global__ void fix_strips() {
    int i = threadIdx.x;
    if (i >= 120) return;
    size_t off = (size_t)blockIdx.y * TOUT + blockIdx.x * HOP + 272 + i;
    float v = g_y[off];
    __nv_bfloat16 hi = __float2bfloat16(v);
    g_yhi[off] = hi;
    g_ylo[off] = __float2bfloat16(v - __bfloat162float(hi));
}

// ---------------------------------------------------------------------------
// conv_kernel: overlap-add FFT conv, radix-4 Stockham (4 r4 stages + 1 r2).
// Two real rows packed into one complex signal (real symmetric multiplier).
// Exclusive region writes bf16 hi/lo directly; strips atomicAdd fp32.
// ---------------------------------------------------------------------------
__device__ __forceinline__ float2 cmul(float2 a, float2 b) {
    return make_float2(fmaf(a.x, b.x, -a.y * b.y), fmaf(a.x, b.y, a.y * b.x));
}
__device__ __forceinline__ float2 cadd(float2 a, float2 b) { return make_float2(a.x+b.x, a.y+b.y); }
__device__ __forceinline__ float2 csub(float2 a, float2 b) { return make_float2(a.x-b.x, a.y-b.y); }

__global__ __launch_bounds__(128) void conv_kernel(
    const float* __restrict__ noise, const float* __restrict__ kf)
{
    __shared__ float2 bufA[NFFT];
    __shared__ float2 bufB[NFFT];
    __shared__ float2 tw[NFFT];    // tw[j] = exp(-i*2*pi*j/512)
    __shared__ float  ks[257];

    const int tid = threadIdx.x;          // 128 threads
    const int b   = blockIdx.x;
    const int q   = blockIdx.y;
    const int row0 = 2 * q, row1 = 2 * q + 1;
    const int base = b * HOP;

    #pragma unroll
    for (int h = 0; h < 4; h++) {
        int j = tid + 128 * h;
        float s, c;
        sincospif(-(float)j * (1.0f / 256.0f), &s, &c);
        tw[j] = make_float2(c, s);
    }
    for (int i = tid; i < 257; i += 128) ks[i] = kf[i];

    const float* n0 = noise + (size_t)row0 * TPAD;
    const float* n1 = noise + (size_t)row1 * TPAD;
    #pragma unroll
    for (int h = 0; h < 4; h++) {
        int i = tid + 128 * h;
        float v0 = 0.f, v1 = 0.f;
        int p = base + i;
        if (i < HOP && p < TPAD) { v0 = n0[p]; v1 = n1[p]; }
        bufA[i] = make_float2(v0, v1);
    }
    __syncthreads();

    float2* src = bufA;
    float2* dst = bufB;

    // ---- forward FFT: 4 radix-4 Stockham stages (m = 1,4,16,64) ----
    #pragma unroll
    for (int s = 0; s < 4; s++) {
        const int m = 1 << (2 * s);
        const int j = tid;                 // 0..127
        const int e = j & ~(m - 1);        // q*m
        const int p = j & (m - 1);
        float2 c0 = src[j], c1 = src[j + 128], c2 = src[j + 256], c3 = src[j + 384];
        float2 A = cadd(c0, c2), B = csub(c0, c2), C = cadd(c1, c3);
        float2 dd = csub(c1, c3);
        float2 D = make_float2(dd.y, -dd.x);          // -i*(c1-c3)
        int o = 4 * e + p;
        dst[o]         = cadd(A, C);
        dst[o + m]     = cmul(tw[e],     cadd(B, D));
        dst[o + 2*m]   = cmul(tw[2*e],   csub(A, C));
        dst[o + 3*m]   = cmul(tw[3*e],   csub(B, D));
        float2* t = src; src = dst; dst = t;
        __syncthreads();
    }
    // final radix-2 stage (m=256, twiddle = 1)
    #pragma unroll
    for (int h = 0; h < 2; h++) {
        int j = tid + 128 * h;
        float2 c0 = src[j], c1 = src[j + 256];
        dst[j]       = cadd(c0, c1);
        dst[j + 256] = csub(c0, c1);
    }
    { float2* t = src; src = dst; dst = t; }
    __syncthreads();

    // ---- spectrum multiply by real symmetric extension of kernel_fft ----
    #pragma unroll
    for (int h = 0; h < 4; h++) {
        int k  = tid + 128 * h;
        int kk = (k <= 256) ? k : (NFFT - k);
        float sc = ks[kk];
        float2 v = src[k];
        src[k] = make_float2(v.x * sc, v.y * sc);
    }
    __syncthreads();

    // ---- inverse FFT (conjugate twiddles, D sign flipped) ----
    #pragma unroll
    for (int s = 0; s < 4; s++) {
        const int m = 1 << (2 * s);
        const int j = tid;
        const int e = j & ~(m - 1);
        const int p = j & (m - 1);
        float2 c0 = src[j], c1 = src[j + 128], c2 = src[j + 256], c3 = src[j + 384];
        float2 A = cadd(c0, c2), B = csub(c0, c2), C = cadd(c1, c3);
        float2 dd = csub(c1, c3);
        float2 D = make_float2(-dd.y, dd.x);          // +i*(c1-c3)
        float2 w1 = tw[e], w2 = tw[2*e], w3 = tw[3*e];
        w1.y = -w1.y; w2.y = -w2.y; w3.y = -w3.y;
        int o = 4 * e + p;
        dst[o]       = cadd(A, C);
        dst[o + m]   = cmul(w1, cadd(B, D));
        dst[o + 2*m] = cmul(w2, csub(A, C));
        dst[o + 3*m] = cmul(w3, csub(B, D));
        float2* t = src; src = dst; dst = t;
        __syncthreads();
    }
    #pragma unroll
    for (int h = 0; h < 2; h++) {
        int j = tid + 128 * h;
        float2 c0 = src[j], c1 = src[j + 256];
        dst[j]       = cadd(c0, c1);
        dst[j + 256] = csub(c0, c1);
    }
    { float2* t = src; src = dst; dst = t; }
    __syncthreads();

    // ---- overlap-add write-out (slice offset 120). 1/512 scale here. ----
    const float inv = 1.0f / (float)NFFT;
    const size_t r0off = (size_t)row0 * TOUT;
    const size_t r1off = (size_t)row1 * TOUT;
    #pragma unroll
    for (int h = 0; h < 4; h++) {
        int j = tid + 128 * h;
        int t = base + j - (S2 - 1);
        if (t < 0 || t >= TOUT) continue;
        float2 v = src[j];
        float v0 = v.x * inv, v1 = v.y * inv;
        if (j >= (S2 - 1) && j < HOP) {       // exclusive: write bf16 hi/lo
            __nv_bfloat16 h0 = __float2bfloat16(v0);
            __nv_bfloat16 h1 = __float2bfloat16(v1);
            g_yhi[r0off + t] = h0;
            g_yhi[r1off + t] = h1;
            g_ylo[r0off + t] = __float2bfloat16(v0 - __bfloat162float(h0));
            g_ylo[r1off + t] = __float2bfloat16(v1 - __bfloat162float(h1));
        } else {                              // overlap strips: fp32 atomic
            atomicAdd(&g_y[r0off + t], v0);
            atomicAdd(&g_y[r1off + t], v1);
        }
    }
}

// ---------------------------------------------------------------------------
// GEMM v2: bf16 tensor-core with 3-term split, cp.async 4-stage pipeline.
//   C[t][d] = sum_c y[c][t] * W[d][c],   passes: Ahi*Whi, Alo*Whi, Ahi*Wlo
// ---------------------------------------------------------------------------
#define BM 128
#define BN 128
#define BK 32
#define ASTRIDE (BM + 8)        // 136 bf16 (272B rows, 16B multiple)
#define BSTRIDE (BK + 8)        // 40 bf16 (80B rows, 16B multiple)
#define ABUF (BK * ASTRIDE)     // 4352 elems / stage
#define BBUF (BN * BSTRIDE)     // 5120 elems / stage
#define NSTAGE 4
#define GEMM_SMEM (NSTAGE * (ABUF + BBUF) * 2)   // 75776 bytes

__device__ __forceinline__ uint32_t smem_u32(const void* p) {
    return (uint32_t)__cvta_generic_to_shared(p);
}
__device__ __forceinline__ void cp16(void* dst, const void* src) {
    asm volatile("cp.async.ca.shared.global [%0], [%1], 16;\n"
                 :: "r"(smem_u32(dst)), "l"(src));
}
__device__ __forceinline__ void cp_commit() { asm volatile("cp.async.commit_group;\n"); }
__device__ __forceinline__ void cp_wait2()  { asm volatile("cp.async.wait_group 2;\n"); }

__device__ __forceinline__ void ldmT4(uint32_t* r, uint32_t addr) {
    asm volatile("ldmatrix.sync.aligned.m8n8.x4.trans.shared.b16 {%0,%1,%2,%3},[%4];\n"
                 : "=r"(r[0]), "=r"(r[1]), "=r"(r[2]), "=r"(r[3]) : "r"(addr));
}
__device__ __forceinline__ void ldmN4(uint32_t* r, uint32_t addr) {
    asm volatile("ldmatrix.sync.aligned.m8n8.x4.shared.b16 {%0,%1,%2,%3},[%4];\n"
                 : "=r"(r[0]), "=r"(r[1]), "=r"(r[2]), "=r"(r[3]) : "r"(addr));
}
__device__ __forceinline__ void mma16816(float* c, const uint32_t* a, const uint32_t* b) {
    asm volatile("mma.sync.aligned.m16n8k16.row.col.f32.bf16.bf16.f32 "
                 "{%0,%1,%2,%3},{%4,%5,%6,%7},{%8,%9},{%0,%1,%2,%3};\n"
                 : "+f"(c[0]), "+f"(c[1]), "+f"(c[2]), "+f"(c[3])
                 : "r"(a[0]), "r"(a[1]), "r"(a[2]), "r"(a[3]), "r"(b[0]), "r"(b[1]));
}

__global__ __launch_bounds__(256, 2) void gemm_bf16(float* __restrict__ out) {
    extern __shared__ __align__(16) unsigned char smem_raw[];
    __nv_bfloat16* As = reinterpret_cast<__nv_bfloat16*>(smem_raw);
    __nv_bfloat16* Bs = As + NSTAGE * ABUF;

    const int tid  = threadIdx.x;
    const int lane = tid & 31;
    const int w    = tid >> 5;
    const int wm   = w & 1;        // m-half (64)
    const int wn   = w >> 1;       // n-quarter (32)

    const int d0 = blockIdx.x * BN;
    const int t0 = blockIdx.y * BM;
    const int z  = blockIdx.z;

    // cp.async per-thread mapping
    const int ak0 = tid >> 4;             // A k-row (second: +16)
    const int am0 = (tid & 15) * 8;       // A m offset (elems)
    const int bn0 = tid >> 2;             // B n-row (second: +64)
    const int bk0 = (tid & 3) * 8;        // B k offset (elems)

    auto issue = [&](int kt, int stg) {
        const int pn   = kt / 12;                       // 0:hi*hi 1:lo*hi 2:hi*lo
        const int ksrc = (kt - pn * 12) * BK;
        const __nv_bfloat16* Ag = (pn == 1 ? g_ylo : g_yhi)
                                  + ((size_t)(z * CCH + ksrc)) * TOUT + t0;
        const __nv_bfloat16* Bg = (pn == 2 ? g_Wlo : g_Whi)
                                  + (size_t)d0 * CCH + ksrc;
        __nv_bfloat16* Asd = As + stg * ABUF;
        __nv_bfloat16* Bsd = Bs + stg * BBUF;
        cp16(&Asd[ak0 * ASTRIDE + am0],        Ag + (size_t)ak0 * TOUT + am0);
        cp16(&Asd[(ak0 + 16) * ASTRIDE + am0], Ag + (size_t)(ak0 + 16) * TOUT + am0);
        cp16(&Bsd[bn0 * BSTRIDE + bk0],        Bg + (size_t)bn0 * CCH + bk0);
        cp16(&Bsd[(bn0 + 64) * BSTRIDE + bk0], Bg + (size_t)(bn0 + 64) * CCH + bk0);
    };

    // ldmatrix per-lane offsets
    const int g  = lane >> 3, r = lane & 7;
    const int ak = ((g & 2) << 2) + r;    // k row (+8 for upper pair)
    const int amo = (g & 1) << 3;         // m +8 for odd pair
    const int bn = ((g & 2) << 2) + r;
    const int bko = (g & 1) << 3;

    const uint32_t as0 = smem_u32(As);
    const uint32_t bs0 = smem_u32(Bs);
    uint32_t aAddr[4], bAddr[2];
    #pragma unroll
    for (int mi = 0; mi < 4; mi++)
        aAddr[mi] = as0 + (uint32_t)((ak * ASTRIDE + wm * 64 + mi * 16 + amo) * 2);
    #pragma unroll
    for (int nj = 0; nj < 2; nj++)
        bAddr[nj] = bs0 + (uint32_t)(((wn * 32 + nj * 16 + bn) * BSTRIDE + bko) * 2);

    float acc[4][4][4];
    #pragma unroll
    for (int i = 0; i < 4; i++)
        #pragma unroll
        for (int j = 0; j < 4; j++)
            #pragma unroll
            for (int k = 0; k < 4; k++) acc[i][j][k] = 0.f;

    const int NKT = 36;

    // prologue: stages 0..2
    #pragma unroll
    for (int s = 0; s < NSTAGE - 1; s++) { issue(s, s); cp_commit(); }

    for (int kt = 0; kt < NKT; kt++) {
        cp_wait2();            // stage kt landed
        __syncthreads();       // visible to all; all done computing kt-1

        const int stg = kt & 3;
        const uint32_t aob = (uint32_t)(stg * ABUF * 2);
        const uint32_t bob = (uint32_t)(stg * BBUF * 2);
        #pragma unroll
        for (int kh = 0; kh < 2; kh++) {
            uint32_t afr[4][4], bfr[2][4];
            #pragma unroll
            for (int mi = 0; mi < 4; mi++)
                ldmT4(afr[mi], aAddr[mi] + aob + (uint32_t)(kh * 16 * ASTRIDE * 2));
            #pragma unroll
            for (int nj = 0; nj < 2; nj++)
                ldmN4(bfr[nj], bAddr[nj] + bob + (uint32_t)(kh * 32));
            #pragma unroll
            for (int mi = 0; mi < 4; mi++)
                #pragma unroll
                for (int n8 = 0; n8 < 4; n8++)
                    mma16816(acc[mi][n8], afr[mi], &bfr[n8 >> 1][(n8 & 1) * 2]);
        }

        if (kt + NSTAGE - 1 < NKT) issue(kt + NSTAGE - 1, (kt + NSTAGE - 1) & 3);
        cp_commit();           // always commit (keeps group-count invariant)
    }

    // epilogue
    const int cm  = lane >> 2;
    const int cn2 = (lane & 3) << 1;
    #pragma unroll
    for (int mi = 0; mi < 4; mi++) {
        const int t = t0 + wm * 64 + mi * 16 + cm;
        float* orow = out + ((size_t)z * TOUT + t) * CCH + d0 + wn * 32 + cn2;
        #pragma unroll
        for (int n8 = 0; n8 < 4; n8++) {
            float* o1 = orow + n8 * 8;
            *(float2*)o1             = make_float2(acc[mi][n8][0], acc[mi][n8][1]);
            *(float2*)(o1 + 8 * CCH) = make_float2(acc[mi][n8][2], acc[mi][n8][3]);
        }
    }
}

// ---------------------------------------------------------------------------
extern "C" void kernel_launch(void* const* d_in, const int* in_sizes, int n_in,
                              void* d_out, int out_size)
{
    const float* noise = (const float*)d_in[0];   // (768, 65656)
    const float* stdv  = (const float*)d_in[1];   // (384,)
    const float* vt    = (const float*)d_in[2];   // (384, 384)
    const float* kf    = (const float*)d_in[3];   // (257,)

    cudaFuncSetAttribute(gemm_bf16, cudaFuncAttributeMaxDynamicSharedMemorySize, GEMM_SMEM);

    prep_w<<<(CCH * CCH + 255) / 256, 256>>>(vt, stdv);
    zero_strips<<<dim3(NB - 1, NROWS), 32>>>();
    conv_kernel<<<dim3(NB, NROWS / 2), 128>>>(noise, kf);
    fix_strips<<<dim3(NB - 1, NROWS), 128>>>();
    gemm_bf16<<<dim3(CCH / BN, TOUT / BM, 2), 256, GEMM_SMEM>>>((float*)d_out);
}

// round 5
// speedup vs baseline: 3.0425x; 1.2370x over previous
#include <cuda_runtime.h>
#include <cuda_bf16.h>
#include <cstdint>

// Problem constants
#define TPAD  65656      // t_padded = T_SIM + T_KERNEL - 1
#define TOUT  65536      // output time samples
#define CCH   384        // channels
#define NROWS 768        // SIZE * C
#define NB    168        // number of OA blocks
#define HOP   392        // BLOCK - s2 + 1
#define S2    121        // kernel length
#define NFFT  512        // OA block size
#define NSTRIP 167       // overlap strips
#define STRIPW 120       // strip width
#define STRIPROW (NSTRIP * STRIPW)   // 20040

// bf16 hi/lo split of the filtered signal y[row][t]
__device__ __align__(256) __nv_bfloat16 g_yhi[(size_t)NROWS * TOUT];
__device__ __align__(256) __nv_bfloat16 g_ylo[(size_t)NROWS * TOUT];
// compact overlap contributions: strip s = tail(block s) + head(block s+1)
__device__ float g_tail[(size_t)NROWS * STRIPROW];
__device__ float g_head[(size_t)NROWS * STRIPROW];
// Precomputed W[d][c] = std[c]*vt[c][d], split into bf16 hi/lo
__device__ __align__(256) __nv_bfloat16 g_Whi[CCH * CCH];
__device__ __align__(256) __nv_bfloat16 g_Wlo[CCH * CCH];
// Precomputed FFT tables
__device__ float2 g_tw[NFFT];     // exp(-i*2*pi*j/512)
__device__ float  g_kss[NFFT];    // symmetric-extended kernel_fft / 512

// ---------------------------------------------------------------------------
__global__ void prep_w(const float* __restrict__ vt, const float* __restrict__ stdv) {
    int i = blockIdx.x * 256 + threadIdx.x;
    if (i < CCH * CCH) {
        int d = i / CCH, c = i % CCH;
        float w = stdv[c] * vt[c * CCH + d];
        __nv_bfloat16 hi = __float2bfloat16(w);
        g_Whi[i] = hi;
        g_Wlo[i] = __float2bfloat16(w - __bfloat162float(hi));
    }
}

__global__ void prep_tw(const float* __restrict__ kf) {
    int j = blockIdx.x * 256 + threadIdx.x;
    if (j < NFFT) {
        float s, c;
        sincospif(-(float)j * (1.0f / 256.0f), &s, &c);
        g_tw[j] = make_float2(c, s);
        int kk = (j <= 256) ? j : (NFFT - j);
        g_kss[j] = kf[kk] * (1.0f / (float)NFFT);
    }
}

// ---------------------------------------------------------------------------
// conv_kernel: overlap-add FFT conv, radix-4 Stockham, heavily fused:
//  - load + forward stage0 in registers
//  - forward final r2 + spectrum multiply + inverse stage0 in registers
//  - inverse final r2 + routed writeout in registers
// Two real rows packed into one complex signal (real symmetric multiplier).
// ---------------------------------------------------------------------------
__device__ __forceinline__ float2 cmul(float2 a, float2 b) {
    return make_float2(fmaf(a.x, b.x, -a.y * b.y), fmaf(a.x, b.y, a.y * b.x));
}
__device__ __forceinline__ float2 cadd(float2 a, float2 b) { return make_float2(a.x+b.x, a.y+b.y); }
__device__ __forceinline__ float2 csub(float2 a, float2 b) { return make_float2(a.x-b.x, a.y-b.y); }
__device__ __forceinline__ float2 cscale(float2 a, float s) { return make_float2(a.x*s, a.y*s); }

__global__ __launch_bounds__(128) void conv_kernel(const float* __restrict__ noise)
{
    __shared__ float2 bufA[NFFT];
    __shared__ float2 bufB[NFFT];
    __shared__ float2 tw[NFFT];

    const int tid = threadIdx.x;          // 128 threads
    const int b   = blockIdx.x;           // OA block
    const int q   = blockIdx.y;           // row pair
    const int row0 = 2 * q, row1 = 2 * q + 1;
    const int base = b * HOP;

    // issue input loads early
    const float* n0 = noise + (size_t)row0 * TPAD;
    const float* n1 = noise + (size_t)row1 * TPAD;
    float2 c[4];
    #pragma unroll
    for (int h = 0; h < 4; h++) {
        int i = tid + 128 * h;
        float v0 = 0.f, v1 = 0.f;
        int p = base + i;
        if (i < HOP && p < TPAD) { v0 = __ldg(n0 + p); v1 = __ldg(n1 + p); }
        c[h] = make_float2(v0, v1);
    }
    // prefetch spectrum scales for the fused middle step
    float kss0 = g_kss[tid], kss1 = g_kss[tid + 128];
    float kss2 = g_kss[tid + 256], kss3 = g_kss[tid + 384];

    // twiddle table to smem
    #pragma unroll
    for (int h = 0; h < 4; h++) {
        int j = tid + 128 * h;
        tw[j] = g_tw[j];
    }
    __syncthreads();

    float2* src = bufA;
    float2* dst = bufB;

    // ---- forward stage 0 (m=1) fused with load: inputs already in regs ----
    {
        float2 A = cadd(c[0], c[2]), B = csub(c[0], c[2]), C = cadd(c[1], c[3]);
        float2 dd = csub(c[1], c[3]);
        float2 D = make_float2(dd.y, -dd.x);          // -i*(c1-c3)
        int o = 4 * tid;
        dst[o]     = cadd(A, C);
        dst[o + 1] = cmul(tw[tid],     cadd(B, D));
        dst[o + 2] = cmul(tw[2 * tid], csub(A, C));
        dst[o + 3] = cmul(tw[3 * tid], csub(B, D));
    }
    { float2* t = src; src = dst; dst = t; }      // src = bufB
    __syncthreads();

    // ---- forward stages 1..3 (m = 4, 16, 64) ----
    #pragma unroll
    for (int s = 1; s < 4; s++) {
        const int m = 1 << (2 * s);
        const int j = tid;
        const int e = j & ~(m - 1);
        const int p = j & (m - 1);
        float2 c0 = src[j], c1 = src[j + 128], c2 = src[j + 256], c3 = src[j + 384];
        float2 A = cadd(c0, c2), B = csub(c0, c2), C = cadd(c1, c3);
        float2 dd = csub(c1, c3);
        float2 D = make_float2(dd.y, -dd.x);
        int o = 4 * e + p;
        dst[o]       = cadd(A, C);
        dst[o + m]   = cmul(tw[e],     cadd(B, D));
        dst[o + 2*m] = cmul(tw[2*e],   csub(A, C));
        dst[o + 3*m] = cmul(tw[3*e],   csub(B, D));
        float2* t = src; src = dst; dst = t;
        __syncthreads();
    }
    // src = bufA (after 3 swaps from bufB)

    // ---- fused: forward final r2 (m=256, tw=1) + spectrum scale + inverse
    //      stage 0 (m=1) — the thread that produces {t, t+128, t+256, t+384}
    //      is exactly the one that consumes them, so all in registers ----
    {
        float2 a0 = src[tid], a1 = src[tid + 128];
        float2 a2 = src[tid + 256], a3 = src[tid + 384];
        float2 f0 = cscale(cadd(a0, a2), kss0);    // spectrum idx tid
        float2 f1 = cscale(cadd(a1, a3), kss1);    // idx tid+128
        float2 f2 = cscale(csub(a0, a2), kss2);    // idx tid+256
        float2 f3 = cscale(csub(a1, a3), kss3);    // idx tid+384
        // inverse stage 0: c0=f0, c1=f1, c2=f2, c3=f3 (indices j, j+128, j+256, j+384)
        float2 A = cadd(f0, f2), B = csub(f0, f2), C = cadd(f1, f3);
        float2 dd = csub(f1, f3);
        float2 D = make_float2(-dd.y, dd.x);       // +i*(c1-c3)
        float2 w1 = tw[tid], w2 = tw[2 * tid], w3 = tw[3 * tid];
        w1.y = -w1.y; w2.y = -w2.y; w3.y = -w3.y;
        int o = 4 * tid;
        dst[o]     = cadd(A, C);
        dst[o + 1] = cmul(w1, cadd(B, D));
        dst[o + 2] = cmul(w2, csub(A, C));
        dst[o + 3] = cmul(w3, csub(B, D));
    }
    { float2* t = src; src = dst; dst = t; }      // src = bufB
    __syncthreads();

    // ---- inverse stages 1..3 ----
    #pragma unroll
    for (int s = 1; s < 4; s++) {
        const int m = 1 << (2 * s);
        const int j = tid;
        const int e = j & ~(m - 1);
        const int p = j & (m - 1);
        float2 c0 = src[j], c1 = src[j + 128], c2 = src[j + 256], c3 = src[j + 384];
        float2 A = cadd(c0, c2), B = csub(c0, c2), C = cadd(c1, c3);
        float2 dd = csub(c1, c3);
        float2 D = make_float2(-dd.y, dd.x);
        float2 w1 = tw[e], w2 = tw[2*e], w3 = tw[3*e];
        w1.y = -w1.y; w2.y = -w2.y; w3.y = -w3.y;
        int o = 4 * e + p;
        dst[o]       = cadd(A, C);
        dst[o + m]   = cmul(w1, cadd(B, D));
        dst[o + 2*m] = cmul(w2, csub(A, C));
        dst[o + 3*m] = cmul(w3, csub(B, D));
        float2* t = src; src = dst; dst = t;
        __syncthreads();
    }
    // src = bufA

    // ---- inverse final r2 fused with routed writeout ----
    const size_t r0y = (size_t)row0 * TOUT;
    const size_t r1y = (size_t)row1 * TOUT;
    const size_t r0s = (size_t)row0 * STRIPROW;
    const size_t r1s = (size_t)row1 * STRIPROW;

    #pragma unroll
    for (int h = 0; h < 2; h++) {
        const int j = tid + 128 * h;
        float2 c0 = src[j], c1 = src[j + 256];
        float2 outv[2] = { cadd(c0, c1), csub(c0, c1) };
        int idx[2] = { j, j + 256 };
        #pragma unroll
        for (int u = 0; u < 2; u++) {
            const int jj = idx[u];
            const float2 v = outv[u];
            const int t = base + jj - (S2 - 1);
            if (jj >= (S2 - 1) && jj < HOP) {          // exclusive region
                if (t < TOUT) {
                    __nv_bfloat16 h0 = __float2bfloat16(v.x);
                    __nv_bfloat16 h1 = __float2bfloat16(v.y);
                    g_yhi[r0y + t] = h0;
                    g_yhi[r1y + t] = h1;
                    g_ylo[r0y + t] = __float2bfloat16(v.x - __bfloat162float(h0));
                    g_ylo[r1y + t] = __float2bfloat16(v.y - __bfloat162float(h1));
                }
            } else if (jj < (S2 - 1)) {                // head -> strip b-1
                if (b > 0) {
                    g_head[r0s + (b - 1) * STRIPW + jj] = v.x;
                    g_head[r1s + (b - 1) * STRIPW + jj] = v.y;
                }
            } else {                                   // tail -> strip b
                if (b < NSTRIP) {
                    g_tail[r0s + b * STRIPW + (jj - HOP)] = v.x;
                    g_tail[r1s + b * STRIPW + (jj - HOP)] = v.y;
                }
            }
        }
    }
}

// ---------------------------------------------------------------------------
// fix2: strip s value = tail(block s) + head(block s+1); emit bf16 hi/lo.
// ---------------------------------------------------------------------------
__global__ __launch_bounds__(256) void fix2() {
    const int row = blockIdx.x;
    const float* tp = g_tail + (size_t)row * STRIPROW;
    const float* hp = g_head + (size_t)row * STRIPROW;
    const size_t yb = (size_t)row * TOUT;
    for (int idx = threadIdx.x; idx < STRIPROW; idx += 256) {
        int s = idx / STRIPW;
        int i = idx - s * STRIPW;
        float v = tp[idx] + hp[idx];
        int t = s * HOP + 272 + i;
        __nv_bfloat16 hi = __float2bfloat16(v);
        g_yhi[yb + t] = hi;
        g_ylo[yb + t] = __float2bfloat16(v - __bfloat162float(hi));
    }
}

// ---------------------------------------------------------------------------
// GEMM: bf16 tensor-core, 3-term split, BK=64, 3-stage cp.async pipeline.
//   C[t][d] = sum_c y[c][t] * W[d][c],   passes: Ahi*Whi, Alo*Whi, Ahi*Wlo
// ---------------------------------------------------------------------------
#define BM 128
#define BN 128
#define BK 64
#define ASTRIDE (BM + 8)        // 136 bf16
#define BSTRIDE (BK + 8)        // 72 bf16
#define ABUF (BK * ASTRIDE)     // 8704 elems / stage
#define BBUF (BN * BSTRIDE)     // 9216 elems / stage
#define NSTAGE 3
#define GEMM_SMEM (NSTAGE * (ABUF + BBUF) * 2)   // 107520 bytes

__device__ __forceinline__ uint32_t smem_u32(const void* p) {
    return (uint32_t)__cvta_generic_to_shared(p);
}
__device__ __forceinline__ void cp16(void* dst, const void* src) {
    asm volatile("cp.async.ca.shared.global [%0], [%1], 16;\n"
                 :: "r"(smem_u32(dst)), "l"(src));
}
__device__ __forceinline__ void cp_commit() { asm volatile("cp.async.commit_group;\n"); }
__device__ __forceinline__ void cp_wait1()  { asm volatile("cp.async.wait_group 1;\n"); }

__device__ __forceinline__ void ldmT4(uint32_t* r, uint32_t addr) {
    asm volatile("ldmatrix.sync.aligned.m8n8.x4.trans.shared.b16 {%0,%1,%2,%3},[%4];\n"
                 : "=r"(r[0]), "=r"(r[1]), "=r"(r[2]), "=r"(r[3]) : "r"(addr));
}
__device__ __forceinline__ void ldmN4(uint32_t* r, uint32_t addr) {
    asm volatile("ldmatrix.sync.aligned.m8n8.x4.shared.b16 {%0,%1,%2,%3},[%4];\n"
                 : "=r"(r[0]), "=r"(r[1]), "=r"(r[2]), "=r"(r[3]) : "r"(addr));
}
__device__ __forceinline__ void mma16816(float* c, const uint32_t* a, const uint32_t* b) {
    asm volatile("mma.sync.aligned.m16n8k16.row.col.f32.bf16.bf16.f32 "
                 "{%0,%1,%2,%3},{%4,%5,%6,%7},{%8,%9},{%0,%1,%2,%3};\n"
                 : "+f"(c[0]), "+f"(c[1]), "+f"(c[2]), "+f"(c[3])
                 : "r"(a[0]), "r"(a[1]), "r"(a[2]), "r"(a[3]), "r"(b[0]), "r"(b[1]));
}

__global__ __launch_bounds__(256, 2) void gemm_bf16(float* __restrict__ out) {
    extern __shared__ __align__(16) unsigned char smem_raw[];
    __nv_bfloat16* As = reinterpret_cast<__nv_bfloat16*>(smem_raw);
    __nv_bfloat16* Bs = As + NSTAGE * ABUF;

    const int tid  = threadIdx.x;
    const int lane = tid & 31;
    const int w    = tid >> 5;
    const int wm   = w & 1;        // m-half (64)
    const int wn   = w >> 1;       // n-quarter (32)

    const int d0 = blockIdx.x * BN;    // 3 d-tiles vary fastest -> A reuse in L2
    const int t0 = blockIdx.y * BM;
    const int z  = blockIdx.z;

    // cp.async mappings (1024 16B-chunks per tile, 4 per thread)
    // A chunk: k = cid>>4 (0..63), m = (cid&15)*8
    // B chunk: n = cid>>3 (0..127), k = (cid&7)*8
    auto issue = [&](int kt, int stg) {
        const int pn   = kt / 6;                        // 0:hi*hi 1:lo*hi 2:hi*lo
        const int ksrc = (kt - pn * 6) * BK;
        const __nv_bfloat16* Ag = (pn == 1 ? g_ylo : g_yhi)
                                  + ((size_t)(z * CCH + ksrc)) * TOUT + t0;
        const __nv_bfloat16* Bg = (pn == 2 ? g_Wlo : g_Whi)
                                  + (size_t)d0 * CCH + ksrc;
        __nv_bfloat16* Asd = As + stg * ABUF;
        __nv_bfloat16* Bsd = Bs + stg * BBUF;
        #pragma unroll
        for (int i = 0; i < 4; i++) {
            int cid = tid + 256 * i;
            int ka = cid >> 4, ma = (cid & 15) * 8;
            cp16(&Asd[ka * ASTRIDE + ma], Ag + (size_t)ka * TOUT + ma);
        }
        #pragma unroll
        for (int i = 0; i < 4; i++) {
            int cid = tid + 256 * i;
            int nb = cid >> 3, kb = (cid & 7) * 8;
            cp16(&Bsd[nb * BSTRIDE + kb], Bg + (size_t)nb * CCH + kb);
        }
    };

    // ldmatrix per-lane offsets
    const int g  = lane >> 3, r = lane & 7;
    const int ak = ((g & 2) << 2) + r;    // k row within 16 (+8 upper pair)
    const int amo = (g & 1) << 3;         // m +8 odd pair
    const int bn = ((g & 2) << 2) + r;
    const int bko = (g & 1) << 3;

    const uint32_t as0 = smem_u32(As);
    const uint32_t bs0 = smem_u32(Bs);
    uint32_t aAddr[4], bAddr[2];
    #pragma unroll
    for (int mi = 0; mi < 4; mi++)
        aAddr[mi] = as0 + (uint32_t)((ak * ASTRIDE + wm * 64 + mi * 16 + amo) * 2);
    #pragma unroll
    for (int nj = 0; nj < 2; nj++)
        bAddr[nj] = bs0 + (uint32_t)(((wn * 32 + nj * 16 + bn) * BSTRIDE + bko) * 2);

    float acc[4][4][4];
    #pragma unroll
    for (int i = 0; i < 4; i++)
        #pragma unroll
        for (int j = 0; j < 4; j++)
            #pragma unroll
            for (int k = 0; k < 4; k++) acc[i][j][k] = 0.f;

    const int NKT = 18;     // K' = 1152 / 64

    #pragma unroll
    for (int s = 0; s < NSTAGE - 1; s++) { issue(s, s); cp_commit(); }

    for (int kt = 0; kt < NKT; kt++) {
        cp_wait1();            // stage kt landed
        __syncthreads();

        const int stg = kt % NSTAGE;
        const uint32_t aob = (uint32_t)(stg * ABUF * 2);
        const uint32_t bob = (uint32_t)(stg * BBUF * 2);
        #pragma unroll
        for (int kh = 0; kh < 4; kh++) {
            uint32_t afr[4][4], bfr[2][4];
            #pragma unroll
            for (int mi = 0; mi < 4; mi++)
                ldmT4(afr[mi], aAddr[mi] + aob + (uint32_t)(kh * 16 * ASTRIDE * 2));
            #pragma unroll
            for (int nj = 0; nj < 2; nj++)
                ldmN4(bfr[nj], bAddr[nj] + bob + (uint32_t)(kh * 32));
            #pragma unroll
            for (int mi = 0; mi < 4; mi++)
                #pragma unroll
                for (int n8 = 0; n8 < 4; n8++)
                    mma16816(acc[mi][n8], afr[mi], &bfr[n8 >> 1][(n8 & 1) * 2]);
        }

        if (kt + NSTAGE - 1 < NKT) issue(kt + NSTAGE - 1, (kt + NSTAGE - 1) % NSTAGE);
        cp_commit();
    }

    // epilogue
    const int cm  = lane >> 2;
    const int cn2 = (lane & 3) << 1;
    #pragma unroll
    for (int mi = 0; mi < 4; mi++) {
        const int t = t0 + wm * 64 + mi * 16 + cm;
        float* orow = out + ((size_t)z * TOUT + t) * CCH + d0 + wn * 32 + cn2;
        #pragma unroll
        for (int n8 = 0; n8 < 4; n8++) {
            float* o1 = orow + n8 * 8;
            *(float2*)o1             = make_float2(acc[mi][n8][0], acc[mi][n8][1]);
            *(float2*)(o1 + 8 * CCH) = make_float2(acc[mi][n8][2], acc[mi][n8][3]);
        }
    }
}

// ---------------------------------------------------------------------------
extern "C" void kernel_launch(void* const* d_in, const int* in_sizes, int n_in,
                              void* d_out, int out_size)
{
    const float* noise = (const float*)d_in[0];   // (768, 65656)
    const float* stdv  = (const float*)d_in[1];   // (384,)
    const float* vt    = (const float*)d_in[2];   // (384, 384)
    const float* kf    = (const float*)d_in[3];   // (257,)

    cudaFuncSetAttribute(gemm_bf16, cudaFuncAttributeMaxDynamicSharedMemorySize, GEMM_SMEM);

    prep_w<<<(CCH * CCH + 255) / 256, 256>>>(vt, stdv);
    prep_tw<<<2, 256>>>(kf);
    conv_kernel<<<dim3(NB, NROWS / 2), 128>>>(noise);
    fix2<<<NROWS, 256>>>();
    gemm_bf16<<<dim3(CCH / BN, TOUT / BM, 2), 256, GEMM_SMEM>>>((float*)d_out);
}

// round 8
// speedup vs baseline: 3.6303x; 1.1932x over previous
#include <cuda_runtime.h>
#include <cuda_fp16.h>
#include <cstdint>

// Problem constants
#define TPAD  65656      // t_padded = T_SIM + T_KERNEL - 1
#define TOUT  65536      // output time samples
#define CCH   384        // channels
#define NROWS 768        // SIZE * C
#define NB    168        // number of OA blocks
#define HOP   392        // BLOCK - s2 + 1
#define S2    121        // kernel length
#define NFFT  512        // OA block size
#define NCHUNK 4
#define BLKS_PER_CHUNK 42    // 4*42 = 168

// fp16 hi/lo split of the filtered signal y[row][t]
__device__ __align__(256) __half g_yhi[(size_t)NROWS * TOUT];
__device__ __align__(256) __half g_ylo[(size_t)NROWS * TOUT];
// chunk-boundary strip contributions (3 strips per row: b = 41, 83, 125)
__device__ float g_bt[NROWS][3][120];     // tail of blocks 41/83/125
__device__ float g_bh[NROWS][3][120];     // head of blocks 42/84/126
// Precomputed W[d][c] = std[c]*vt[c][d] in fp16 (hi only; 2-term split)
__device__ __align__(256) __half g_Whi[CCH * CCH];
// Precomputed FFT tables
__device__ float2 g_tw[NFFT];     // exp(-i*2*pi*j/512)
__device__ float  g_kss[NFFT];    // symmetric-extended kernel_fft / 512

// ---------------------------------------------------------------------------
__device__ __forceinline__ uint32_t smem_u32(const void* p) {
    return (uint32_t)__cvta_generic_to_shared(p);
}
__device__ __forceinline__ void cp16(void* dst, const void* src) {
    asm volatile("cp.async.ca.shared.global [%0], [%1], 16;\n"
                 :: "r"(smem_u32(dst)), "l"(src));
}
__device__ __forceinline__ void cp_commit() { asm volatile("cp.async.commit_group;\n"); }
__device__ __forceinline__ void cp_wait1()  { asm volatile("cp.async.wait_group 1;\n"); }

// ---------------------------------------------------------------------------
__global__ void prep_w(const float* __restrict__ vt, const float* __restrict__ stdv) {
    int i = blockIdx.x * 256 + threadIdx.x;
    if (i < CCH * CCH) {
        int d = i / CCH, c = i % CCH;
        g_Whi[i] = __float2half_rn(stdv[c] * vt[c * CCH + d]);
    }
}

__global__ void prep_tw(const float* __restrict__ kf) {
    int j = blockIdx.x * 256 + threadIdx.x;
    if (j < NFFT) {
        float s, c;
        sincospif(-(float)j * (1.0f / 256.0f), &s, &c);
        g_tw[j] = make_float2(c, s);
        int kk = (j <= 256) ? j : (NFFT - j);
        g_kss[j] = kf[kk] * (1.0f / (float)NFFT);
    }
}

// ---------------------------------------------------------------------------
// conv_kernel: each CTA processes 42 consecutive OA blocks of one row pair.
// Radix-4 Stockham FFT, fused first/middle/last stages; tail->head overlap
// resolved through a double-buffered smem carry (no global atomics/fixups
// except at the 3 chunk boundaries). Next block's input is cp.async-prefetched.
// ---------------------------------------------------------------------------
__device__ __forceinline__ float2 cmul(float2 a, float2 b) {
    return make_float2(fmaf(a.x, b.x, -a.y * b.y), fmaf(a.x, b.y, a.y * b.x));
}
__device__ __forceinline__ float2 cadd(float2 a, float2 b) { return make_float2(a.x+b.x, a.y+b.y); }
__device__ __forceinline__ float2 csub(float2 a, float2 b) { return make_float2(a.x-b.x, a.y-b.y); }
__device__ __forceinline__ float2 cscale(float2 a, float s) { return make_float2(a.x*s, a.y*s); }

__global__ __launch_bounds__(128) void conv_kernel(const float* __restrict__ noise)
{
    __shared__ float2 bufA[NFFT];
    __shared__ float2 bufB[NFFT];
    __shared__ float2 tw[NFFT];
    __shared__ float2 carry[2][120];
    __shared__ __align__(16) float4 stage[2][2][98];   // [buf][row][16B chunk]

    const int tid = threadIdx.x;          // 128 threads
    const int ch  = blockIdx.x;           // chunk 0..3
    const int q   = blockIdx.y;           // row pair
    const int row0 = 2 * q, row1 = 2 * q + 1;

    const float* n0 = noise + (size_t)row0 * TPAD;
    const float* n1 = noise + (size_t)row1 * TPAD;

    // twiddles + spectrum scales loaded once per CTA
    #pragma unroll
    for (int h = 0; h < 4; h++) tw[tid + 128 * h] = g_tw[tid + 128 * h];
    const float kss0 = g_kss[tid],       kss1 = g_kss[tid + 128];
    const float kss2 = g_kss[tid + 256], kss3 = g_kss[tid + 384];

    auto issue_stage = [&](int k) {
        const int sb = k & 1;
        const int base = (ch * BLKS_PER_CHUNK + k) * HOP;
        #pragma unroll
        for (int u2 = 0; u2 < 2; u2++) {
            int cid = tid + 128 * u2;
            if (cid < 196) {
                int r  = (cid >= 98) ? 1 : 0;
                int c4 = cid - r * 98;
                float4* dstp = &stage[sb][r][c4];
                int p0 = base + c4 * 4;
                if (p0 + 4 <= TPAD) cp16(dstp, (r ? n1 : n0) + p0);
                else                *dstp = make_float4(0.f, 0.f, 0.f, 0.f);
            }
        }
    };

    issue_stage(0);
    cp_commit();

    const size_t r0y = (size_t)row0 * TOUT;
    const size_t r1y = (size_t)row1 * TOUT;

    for (int k = 0; k < BLKS_PER_CHUNK; k++) {
        const int b    = ch * BLKS_PER_CHUNK + k;
        const int base = b * HOP;

        if (k + 1 < BLKS_PER_CHUNK) issue_stage(k + 1);
        cp_commit();
        cp_wait1();            // stage k landed
        __syncthreads();       // also orders prev writeout/carry before reuse

        // ---- load block input from staging ----
        const float* s0 = (const float*)stage[k & 1][0];
        const float* s1 = (const float*)stage[k & 1][1];
        float2 c[4];
        #pragma unroll
        for (int h = 0; h < 4; h++) {
            int i = tid + 128 * h;
            c[h] = (i < HOP) ? make_float2(s0[i], s1[i]) : make_float2(0.f, 0.f);
        }

        float2* src = bufA;
        float2* dst = bufB;

        // ---- forward stage 0 (m=1), inputs in regs ----
        {
            float2 A = cadd(c[0], c[2]), B = csub(c[0], c[2]), C = cadd(c[1], c[3]);
            float2 dd = csub(c[1], c[3]);
            float2 D = make_float2(dd.y, -dd.x);
            int o = 4 * tid;
            dst[o]     = cadd(A, C);
            dst[o + 1] = cmul(tw[tid],     cadd(B, D));
            dst[o + 2] = cmul(tw[2 * tid], csub(A, C));
            dst[o + 3] = cmul(tw[3 * tid], csub(B, D));
        }
        { float2* t = src; src = dst; dst = t; }
        __syncthreads();

        // ---- forward stages 1..3 ----
        #pragma unroll
        for (int s = 1; s < 4; s++) {
            const int m = 1 << (2 * s);
            const int e = tid & ~(m - 1);
            const int p = tid & (m - 1);
            float2 c0 = src[tid], c1 = src[tid + 128], c2 = src[tid + 256], c3 = src[tid + 384];
            float2 A = cadd(c0, c2), B = csub(c0, c2), C = cadd(c1, c3);
            float2 dd = csub(c1, c3);
            float2 D = make_float2(dd.y, -dd.x);
            int o = 4 * e + p;
            dst[o]       = cadd(A, C);
            dst[o + m]   = cmul(tw[e],   cadd(B, D));
            dst[o + 2*m] = cmul(tw[2*e], csub(A, C));
            dst[o + 3*m] = cmul(tw[3*e], csub(B, D));
            float2* t = src; src = dst; dst = t;
            __syncthreads();
        }

        // ---- fused: fwd final r2 + spectrum scale + inverse stage 0 ----
        {
            float2 a0 = src[tid],       a1 = src[tid + 128];
            float2 a2 = src[tid + 256], a3 = src[tid + 384];
            float2 f0 = cscale(cadd(a0, a2), kss0);
            float2 f1 = cscale(cadd(a1, a3), kss1);
            float2 f2 = cscale(csub(a0, a2), kss2);
            float2 f3 = cscale(csub(a1, a3), kss3);
            float2 A = cadd(f0, f2), B = csub(f0, f2), C = cadd(f1, f3);
            float2 dd = csub(f1, f3);
            float2 D = make_float2(-dd.y, dd.x);
            float2 w1 = tw[tid], w2 = tw[2 * tid], w3 = tw[3 * tid];
            w1.y = -w1.y; w2.y = -w2.y; w3.y = -w3.y;
            int o = 4 * tid;
            dst[o]     = cadd(A, C);
            dst[o + 1] = cmul(w1, cadd(B, D));
            dst[o + 2] = cmul(w2, csub(A, C));
            dst[o + 3] = cmul(w3, csub(B, D));
        }
        { float2* t = src; src = dst; dst = t; }
        __syncthreads();

        // ---- inverse stages 1..3 ----
        #pragma unroll
        for (int s = 1; s < 4; s++) {
            const int m = 1 << (2 * s);
            const int e = tid & ~(m - 1);
            const int p = tid & (m - 1);
            float2 c0 = src[tid], c1 = src[tid + 128], c2 = src[tid + 256], c3 = src[tid + 384];
            float2 A = cadd(c0, c2), B = csub(c0, c2), C = cadd(c1, c3);
            float2 dd = csub(c1, c3);
            float2 D = make_float2(-dd.y, dd.x);
            float2 w1 = tw[e], w2 = tw[2*e], w3 = tw[3*e];
            w1.y = -w1.y; w2.y = -w2.y; w3.y = -w3.y;
            int o = 4 * e + p;
            dst[o]       = cadd(A, C);
            dst[o + m]   = cmul(w1, cadd(B, D));
            dst[o + 2*m] = cmul(w2, csub(A, C));
            dst[o + 3*m] = cmul(w3, csub(B, D));
            float2* t = src; src = dst; dst = t;
            __syncthreads();
        }
        // src = bufA

        // ---- inverse final r2 fused with routed writeout + carry ----
        float2*       cw = carry[k & 1];          // tail dest (for block k)
        const float2* cr = carry[(k & 1) ^ 1];    // head carry (from block k-1)

        #pragma unroll
        for (int h = 0; h < 2; h++) {
            const int j0 = tid + 128 * h;
            float2 c0 = src[j0], c1 = src[j0 + 256];
            float2 outv[2] = { cadd(c0, c1), csub(c0, c1) };
            int idx[2] = { j0, j0 + 256 };
            #pragma unroll
            for (int u = 0; u < 2; u++) {
                const int jj = idx[u];
                float2 v = outv[u];
                if (jj < S2 - 1) {                         // head (h=0,u=0)
                    if (k == 0) {
                        if (ch > 0) {                      // chunk boundary
                            g_bh[row0][ch - 1][jj] = v.x;
                            g_bh[row1][ch - 1][jj] = v.y;
                        }                                  // b==0: t<0, discard
                    } else {
                        float2 cv = cr[jj];
                        v.x += cv.x; v.y += cv.y;
                        int t = base + jj - (S2 - 1);
                        __half h0 = __float2half_rn(v.x);
                        __half h1 = __float2half_rn(v.y);
                        g_yhi[r0y + t] = h0;
                        g_yhi[r1y + t] = h1;
                        g_ylo[r0y + t] = __float2half_rn(v.x - __half2float(h0));
                        g_ylo[r1y + t] = __float2half_rn(v.y - __half2float(h1));
                    }
                } else if (jj < HOP) {                     // exclusive region
                    int t = base + jj - (S2 - 1);
                    if (t < TOUT) {
                        __half h0 = __float2half_rn(v.x);
                        __half h1 = __float2half_rn(v.y);
                        g_yhi[r0y + t] = h0;
                        g_yhi[r1y + t] = h1;
                        g_ylo[r0y + t] = __float2half_rn(v.x - __half2float(h0));
                        g_ylo[r1y + t] = __float2half_rn(v.y - __half2float(h1));
                    }
                } else {                                   // tail (h=1,u=1)
                    if (k < BLKS_PER_CHUNK - 1) {
                        cw[jj - HOP] = v;
                    } else if (ch < NCHUNK - 1) {          // chunk boundary
                        g_bt[row0][ch][jj - HOP] = v.x;
                        g_bt[row1][ch][jj - HOP] = v.y;
                    }                                      // b==167: t>=TOUT, discard
                }
            }
        }
    }
}

// ---------------------------------------------------------------------------
// fixB: the 3 chunk-boundary strips per row (b = 41, 83, 125).
// ---------------------------------------------------------------------------
__global__ __launch_bounds__(384) void fixB() {
    const int row = blockIdx.x;
    const int idx = threadIdx.x;
    if (idx >= 360) return;
    const int sb = idx / 120;               // 0..2
    const int i  = idx - sb * 120;
    const int b  = BLKS_PER_CHUNK * (sb + 1) - 1;   // 41, 83, 125
    float v = g_bt[row][sb][i] + g_bh[row][sb][i];
    size_t off = (size_t)row * TOUT + b * HOP + 272 + i;
    __half hi = __float2half_rn(v);
    g_yhi[off] = hi;
    g_ylo[off] = __float2half_rn(v - __half2float(hi));
}

// ---------------------------------------------------------------------------
// GEMM: fp16 tensor-core, 2-term split (Ahi*Whi + Alo*Whi), BK=64, 3-stage.
//   C[t][d] = sum_c y[c][t] * W[d][c]
// ---------------------------------------------------------------------------
#define BM 128
#define BN 128
#define BK 64
#define ASTRIDE (BM + 8)        // 136 halves
#define BSTRIDE (BK + 8)        // 72 halves
#define ABUF (BK * ASTRIDE)
#define BBUF (BN * BSTRIDE)
#define NSTAGE 3
#define GEMM_SMEM (NSTAGE * (ABUF + BBUF) * 2)   // 107520 bytes

__device__ __forceinline__ void ldmT4(uint32_t* r, uint32_t addr) {
    asm volatile("ldmatrix.sync.aligned.m8n8.x4.trans.shared.b16 {%0,%1,%2,%3},[%4];\n"
                 : "=r"(r[0]), "=r"(r[1]), "=r"(r[2]), "=r"(r[3]) : "r"(addr));
}
__device__ __forceinline__ void ldmN4(uint32_t* r, uint32_t addr) {
    asm volatile("ldmatrix.sync.aligned.m8n8.x4.shared.b16 {%0,%1,%2,%3},[%4];\n"
                 : "=r"(r[0]), "=r"(r[1]), "=r"(r[2]), "=r"(r[3]) : "r"(addr));
}
__device__ __forceinline__ void mma16816(float* c, const uint32_t* a, const uint32_t* b) {
    asm volatile("mma.sync.aligned.m16n8k16.row.col.f32.f16.f16.f32 "
                 "{%0,%1,%2,%3},{%4,%5,%6,%7},{%8,%9},{%0,%1,%2,%3};\n"
                 : "+f"(c[0]), "+f"(c[1]), "+f"(c[2]), "+f"(c[3])
                 : "r"(a[0]), "r"(a[1]), "r"(a[2]), "r"(a[3]), "r"(b[0]), "r"(b[1]));
}

__global__ __launch_bounds__(256, 2) void gemm_fp16(float* __restrict__ out) {
    extern __shared__ __align__(16) unsigned char smem_raw[];
    __half* As = reinterpret_cast<__half*>(smem_raw);
    __half* Bs = As + NSTAGE * ABUF;

    const int tid  = threadIdx.x;
    const int lane = tid & 31;
    const int w    = tid >> 5;
    const int wm   = w & 1;
    const int wn   = w >> 1;

    const int d0 = blockIdx.x * BN;
    const int t0 = blockIdx.y * BM;
    const int z  = blockIdx.z;

    auto issue = [&](int kt, int stg) {
        const int pn   = kt / 6;                        // 0: Ahi*Whi, 1: Alo*Whi
        const int ksrc = (kt - pn * 6) * BK;
        const __half* Ag = (pn == 1 ? g_ylo : g_yhi)
                           + ((size_t)(z * CCH + ksrc)) * TOUT + t0;
        const __half* Bg = g_Whi + (size_t)d0 * CCH + ksrc;
        __half* Asd = As + stg * ABUF;
        __half* Bsd = Bs + stg * BBUF;
        #pragma unroll
        for (int i = 0; i < 4; i++) {
            int cid = tid + 256 * i;
            int ka = cid >> 4, ma = (cid & 15) * 8;
            cp16(&Asd[ka * ASTRIDE + ma], Ag + (size_t)ka * TOUT + ma);
        }
        #pragma unroll
        for (int i = 0; i < 4; i++) {
            int cid = tid + 256 * i;
            int nb = cid >> 3, kb = (cid & 7) * 8;
            cp16(&Bsd[nb * BSTRIDE + kb], Bg + (size_t)nb * CCH + kb);
        }
    };

    const int g  = lane >> 3, r = lane & 7;
    const int ak = ((g & 2) << 2) + r;
    const int amo = (g & 1) << 3;
    const int bn = ((g & 2) << 2) + r;
    const int bko = (g & 1) << 3;

    const uint32_t as0 = smem_u32(As);
    const uint32_t bs0 = smem_u32(Bs);
    uint32_t aAddr[4], bAddr[2];
    #pragma unroll
    for (int mi = 0; mi < 4; mi++)
        aAddr[mi] = as0 + (uint32_t)((ak * ASTRIDE + wm * 64 + mi * 16 + amo) * 2);
    #pragma unroll
    for (int nj = 0; nj < 2; nj++)
        bAddr[nj] = bs0 + (uint32_t)(((wn * 32 + nj * 16 + bn) * BSTRIDE + bko) * 2);

    float acc[4][4][4];
    #pragma unroll
    for (int i = 0; i < 4; i++)
        #pragma unroll
        for (int j = 0; j < 4; j++)
            #pragma unroll
            for (int k = 0; k < 4; k++) acc[i][j][k] = 0.f;

    const int NKT = 12;     // K' = 768 / 64

    #pragma unroll
    for (int s = 0; s < NSTAGE - 1; s++) { issue(s, s); cp_commit(); }

    for (int kt = 0; kt < NKT; kt++) {
        cp_wait1();
        __syncthreads();

        const int stg = kt % NSTAGE;
        const uint32_t aob = (uint32_t)(stg * ABUF * 2);
        const uint32_t bob = (uint32_t)(stg * BBUF * 2);
        #pragma unroll
        for (int kh = 0; kh < 4; kh++) {
            uint32_t afr[4][4], bfr[2][4];
            #pragma unroll
            for (int mi = 0; mi < 4; mi++)
                ldmT4(afr[mi], aAddr[mi] + aob + (uint32_t)(kh * 16 * ASTRIDE * 2));
            #pragma unroll
            for (int nj = 0; nj < 2; nj++)
                ldmN4(bfr[nj], bAddr[nj] + bob + (uint32_t)(kh * 32));
            #pragma unroll
            for (int mi = 0; mi < 4; mi++)
                #pragma unroll
                for (int n8 = 0; n8 < 4; n8++)
                    mma16816(acc[mi][n8], afr[mi], &bfr[n8 >> 1][(n8 & 1) * 2]);
        }

        if (kt + NSTAGE - 1 < NKT) issue(kt + NSTAGE - 1, (kt + NSTAGE - 1) % NSTAGE);
        cp_commit();
    }

    // epilogue
    const int cm  = lane >> 2;
    const int cn2 = (lane & 3) << 1;
    #pragma unroll
    for (int mi = 0; mi < 4; mi++) {
        const int t = t0 + wm * 64 + mi * 16 + cm;
        float* orow = out + ((size_t)z * TOUT + t) * CCH + d0 + wn * 32 + cn2;
        #pragma unroll
        for (int n8 = 0; n8 < 4; n8++) {
            float* o1 = orow + n8 * 8;
            *(float2*)o1             = make_float2(acc[mi][n8][0], acc[mi][n8][1]);
            *(float2*)(o1 + 8 * CCH) = make_float2(acc[mi][n8][2], acc[mi][n8][3]);
        }
    }
}

// ---------------------------------------------------------------------------
extern "C" void kernel_launch(void* const* d_in, const int* in_sizes, int n_in,
                              void* d_out, int out_size)
{
    const float* noise = (const float*)d_in[0];   // (768, 65656)
    const float* stdv  = (const float*)d_in[1];   // (384,)
    const float* vt    = (const float*)d_in[2];   // (384, 384)
    const float* kf    = (const float*)d_in[3];   // (257,)

    cudaFuncSetAttribute(gemm_fp16, cudaFuncAttributeMaxDynamicSharedMemorySize, GEMM_SMEM);

    prep_w<<<(CCH * CCH + 255) / 256, 256>>>(vt, stdv);
    prep_tw<<<2, 256>>>(kf);
    conv_kernel<<<dim3(NCHUNK, NROWS / 2), 128>>>(noise);
    fixB<<<NROWS, 384>>>();
    gemm_fp16<<<dim3(CCH / BN, TOUT / BM, 2), 256, GEMM_SMEM>>>((float*)d_out);
}

// round 11
// speedup vs baseline: 4.3986x; 1.2116x over previous
#include <cuda_runtime.h>
#include <cuda_fp16.h>
#include <cstdint>

// Problem constants
#define TPAD  65656      // t_padded = T_SIM + T_KERNEL - 1
#define TOUT  65536      // output time samples
#define CCH   384        // channels
#define NROWS 768        // SIZE * C
#define NB    168        // number of OA blocks
#define HOP   392        // BLOCK - s2 + 1
#define S2    121        // kernel length
#define NFFT  512        // OA block size
#define NCHUNK 4
#define BLKS_PER_CHUNK 42    // 4*42 = 168

// fp16 filtered signal y[row][t]
__device__ __align__(256) __half g_yhi[(size_t)NROWS * TOUT];
// chunk-boundary strip contributions (3 strips per row: b = 41, 83, 125)
__device__ float g_bt[NROWS][3][120];     // tail of blocks 41/83/125
__device__ float g_bh[NROWS][3][120];     // head of blocks 42/84/126
// Precomputed W[d][c] = std[c]*vt[c][d] in fp16
__device__ __align__(256) __half g_Whi[CCH * CCH];
// Precomputed FFT tables
__device__ float2 g_tw[NFFT];     // exp(-i*2*pi*j/512)
__device__ float  g_kss[NFFT];    // symmetric-extended kernel_fft / 512

// ---------------------------------------------------------------------------
__device__ __forceinline__ uint32_t smem_u32(const void* p) {
    return (uint32_t)__cvta_generic_to_shared(p);
}
__device__ __forceinline__ void cp16(void* dst, const void* src) {
    asm volatile("cp.async.ca.shared.global [%0], [%1], 16;\n"
                 :: "r"(smem_u32(dst)), "l"(src));
}
__device__ __forceinline__ void cp_commit() { asm volatile("cp.async.commit_group;\n"); }
__device__ __forceinline__ void cp_wait1()  { asm volatile("cp.async.wait_group 1;\n"); }

// ---------------------------------------------------------------------------
__global__ void prep_w(const float* __restrict__ vt, const float* __restrict__ stdv) {
    int i = blockIdx.x * 256 + threadIdx.x;
    if (i < CCH * CCH) {
        int d = i / CCH, c = i % CCH;
        g_Whi[i] = __float2half_rn(stdv[c] * vt[c * CCH + d]);
    }
}

__global__ void prep_tw(const float* __restrict__ kf) {
    int j = blockIdx.x * 256 + threadIdx.x;
    if (j < NFFT) {
        float s, c;
        sincospif(-(float)j * (1.0f / 256.0f), &s, &c);
        g_tw[j] = make_float2(c, s);
        int kk = (j <= 256) ? j : (NFFT - j);
        g_kss[j] = kf[kk] * (1.0f / (float)NFFT);
    }
}

// ---------------------------------------------------------------------------
// conv_kernel: 256 threads run TWO independent complex FFTs (4 noise rows)
// through one barrier schedule. Each CTA owns 42 consecutive OA blocks of its
// 4 rows; tail->head overlap resolved through double-buffered smem carry.
// Radix-4 Stockham, fused first/middle/last stages; cp.async input prefetch.
// ---------------------------------------------------------------------------
__device__ __forceinline__ float2 cmul(float2 a, float2 b) {
    return make_float2(fmaf(a.x, b.x, -a.y * b.y), fmaf(a.x, b.y, a.y * b.x));
}
__device__ __forceinline__ float2 cadd(float2 a, float2 b) { return make_float2(a.x+b.x, a.y+b.y); }
__device__ __forceinline__ float2 csub(float2 a, float2 b) { return make_float2(a.x-b.x, a.y-b.y); }
__device__ __forceinline__ float2 cscale(float2 a, float s) { return make_float2(a.x*s, a.y*s); }

__global__ __launch_bounds__(256) void conv_kernel(const float* __restrict__ noise)
{
    __shared__ float2 bufA[2][NFFT];
    __shared__ float2 bufB[2][NFFT];
    __shared__ float2 tw[NFFT];
    __shared__ float2 carry[2][2][120];                 // [subfft][parity]
    __shared__ __align__(16) float4 stage[2][4][98];    // [parity][row][16B chunk]

    const int tid = threadIdx.x;          // 256 threads
    const int f   = tid >> 7;             // sub-FFT 0/1
    const int t   = tid & 127;            // lane within FFT
    const int ch  = blockIdx.x;           // chunk 0..3
    const int q   = blockIdx.y;           // 4-row group (192)
    const int row0 = 4 * q + 2 * f;       // this sub-FFT's rows
    const int row1 = row0 + 1;

    // twiddles + spectrum scales
    #pragma unroll
    for (int h = 0; h < 2; h++) tw[tid + 256 * h] = g_tw[tid + 256 * h];
    const float kss0 = g_kss[t],       kss1 = g_kss[t + 128];
    const float kss2 = g_kss[t + 256], kss3 = g_kss[t + 384];

    auto issue_stage = [&](int k) {
        const int sb = k & 1;
        const int base = (ch * BLKS_PER_CHUNK + k) * HOP;
        #pragma unroll
        for (int u2 = 0; u2 < 2; u2++) {
            int cid = tid + 256 * u2;
            if (cid < 392) {
                int r  = cid / 98;
                int c4 = cid - r * 98;
                float4* dstp = &stage[sb][r][c4];
                int p0 = base + c4 * 4;
                if (p0 + 4 <= TPAD)
                    cp16(dstp, noise + (size_t)(4 * q + r) * TPAD + p0);
                else
                    *dstp = make_float4(0.f, 0.f, 0.f, 0.f);
            }
        }
    };

    issue_stage(0);
    cp_commit();

    const size_t r0y = (size_t)row0 * TOUT;
    const size_t r1y = (size_t)row1 * TOUT;

    for (int k = 0; k < BLKS_PER_CHUNK; k++) {
        const int b    = ch * BLKS_PER_CHUNK + k;
        const int base = b * HOP;

        if (k + 1 < BLKS_PER_CHUNK) issue_stage(k + 1);
        cp_commit();
        cp_wait1();            // stage k landed
        __syncthreads();       // also orders prev writeout/carry before reuse

        // ---- load block input from staging (this sub-FFT's 2 rows) ----
        const float* s0 = (const float*)stage[k & 1][2 * f];
        const float* s1 = (const float*)stage[k & 1][2 * f + 1];
        float2 c[4];
        #pragma unroll
        for (int h = 0; h < 4; h++) {
            int i = t + 128 * h;
            c[h] = (i < HOP) ? make_float2(s0[i], s1[i]) : make_float2(0.f, 0.f);
        }

        float2* src = bufA[f];
        float2* dst = bufB[f];

        // ---- forward stage 0 (m=1), inputs in regs ----
        {
            float2 A = cadd(c[0], c[2]), B = csub(c[0], c[2]), C = cadd(c[1], c[3]);
            float2 dd = csub(c[1], c[3]);
            float2 D = make_float2(dd.y, -dd.x);
            int o = 4 * t;
            dst[o]     = cadd(A, C);
            dst[o + 1] = cmul(tw[t],     cadd(B, D));
            dst[o + 2] = cmul(tw[2 * t], csub(A, C));
            dst[o + 3] = cmul(tw[3 * t], csub(B, D));
        }
        { float2* x = src; src = dst; dst = x; }
        __syncthreads();

        // ---- forward stages 1..3 ----
        #pragma unroll
        for (int s = 1; s < 4; s++) {
            const int m = 1 << (2 * s);
            const int e = t & ~(m - 1);
            const int p = t & (m - 1);
            float2 c0 = src[t], c1 = src[t + 128], c2 = src[t + 256], c3 = src[t + 384];
            float2 A = cadd(c0, c2), B = csub(c0, c2), C = cadd(c1, c3);
            float2 dd = csub(c1, c3);
            float2 D = make_float2(dd.y, -dd.x);
            int o = 4 * e + p;
            dst[o]       = cadd(A, C);
            dst[o + m]   = cmul(tw[e],   cadd(B, D));
            dst[o + 2*m] = cmul(tw[2*e], csub(A, C));
            dst[o + 3*m] = cmul(tw[3*e], csub(B, D));
            float2* x = src; src = dst; dst = x;
            __syncthreads();
        }

        // ---- fused: fwd final r2 + spectrum scale + inverse stage 0 ----
        {
            float2 a0 = src[t],       a1 = src[t + 128];
            float2 a2 = src[t + 256], a3 = src[t + 384];
            float2 f0 = cscale(cadd(a0, a2), kss0);
            float2 f1 = cscale(cadd(a1, a3), kss1);
            float2 f2 = cscale(csub(a0, a2), kss2);
            float2 f3 = cscale(csub(a1, a3), kss3);
            float2 A = cadd(f0, f2), B = csub(f0, f2), C = cadd(f1, f3);
            float2 dd = csub(f1, f3);
            float2 D = make_float2(-dd.y, dd.x);
            float2 w1 = tw[t], w2 = tw[2 * t], w3 = tw[3 * t];
            w1.y = -w1.y; w2.y = -w2.y; w3.y = -w3.y;
            int o = 4 * t;
            dst[o]     = cadd(A, C);
            dst[o + 1] = cmul(w1, cadd(B, D));
            dst[o + 2] = cmul(w2, csub(A, C));
            dst[o + 3] = cmul(w3, csub(B, D));
        }
        { float2* x = src; src = dst; dst = x; }
        __syncthreads();

        // ---- inverse stages 1..3 ----
        #pragma unroll
        for (int s = 1; s < 4; s++) {
            const int m = 1 << (2 * s);
            const int e = t & ~(m - 1);
            const int p = t & (m - 1);
            float2 c0 = src[t], c1 = src[t + 128], c2 = src[t + 256], c3 = src[t + 384];
            float2 A = cadd(c0, c2), B = csub(c0, c2), C = cadd(c1, c3);
            float2 dd = csub(c1, c3);
            float2 D = make_float2(-dd.y, dd.x);
            float2 w1 = tw[e], w2 = tw[2*e], w3 = tw[3*e];
            w1.y = -w1.y; w2.y = -w2.y; w3.y = -w3.y;
            int o = 4 * e + p;
            dst[o]       = cadd(A, C);
            dst[o + m]   = cmul(w1, cadd(B, D));
            dst[o + 2*m] = cmul(w2, csub(A, C));
            dst[o + 3*m] = cmul(w3, csub(B, D));
            float2* x = src; src = dst; dst = x;
            __syncthreads();
        }
        // src = bufA[f]

        // ---- inverse final r2 fused with routed writeout + carry ----
        float2*       cw = carry[f][k & 1];          // tail dest (block k)
        const float2* cr = carry[f][(k & 1) ^ 1];    // head carry (block k-1)

        #pragma unroll
        for (int h = 0; h < 2; h++) {
            const int j0 = t + 128 * h;
            float2 c0 = src[j0], c1 = src[j0 + 256];
            float2 outv[2] = { cadd(c0, c1), csub(c0, c1) };
            int idx[2] = { j0, j0 + 256 };
            #pragma unroll
            for (int u = 0; u < 2; u++) {
                const int jj = idx[u];
                float2 v = outv[u];
                if (jj < S2 - 1) {                         // head (h=0,u=0)
                    if (k == 0) {
                        if (ch > 0) {                      // chunk boundary
                            g_bh[row0][ch - 1][jj] = v.x;
                            g_bh[row1][ch - 1][jj] = v.y;
                        }                                  // b==0: t<0, discard
                    } else {
                        float2 cv = cr[jj];
                        v.x += cv.x; v.y += cv.y;
                        int tt = base + jj - (S2 - 1);
                        g_yhi[r0y + tt] = __float2half_rn(v.x);
                        g_yhi[r1y + tt] = __float2half_rn(v.y);
                    }
                } else if (jj < HOP) {                     // exclusive region
                    int tt = base + jj - (S2 - 1);
                    if (tt < TOUT) {
                        g_yhi[r0y + tt] = __float2half_rn(v.x);
                        g_yhi[r1y + tt] = __float2half_rn(v.y);
                    }
                } else {                                   // tail (h=1,u=1)
                    if (k < BLKS_PER_CHUNK - 1) {
                        cw[jj - HOP] = v;
                    } else if (ch < NCHUNK - 1) {          // chunk boundary
                        g_bt[row0][ch][jj - HOP] = v.x;
                        g_bt[row1][ch][jj - HOP] = v.y;
                    }                                      // b==167: discard
                }
            }
        }
    }
}

// ---------------------------------------------------------------------------
// fixB: the 3 chunk-boundary strips per row (b = 41, 83, 125).
// ---------------------------------------------------------------------------
__global__ __launch_bounds__(384) void fixB() {
    const int row = blockIdx.x;
    const int idx = threadIdx.x;
    if (idx >= 360) return;
    const int sb = idx / 120;               // 0..2
    const int i  = idx - sb * 120;
    const int b  = BLKS_PER_CHUNK * (sb + 1) - 1;   // 41, 83, 125
    float v = g_bt[row][sb][i] + g_bh[row][sb][i];
    size_t off = (size_t)row * TOUT + b * HOP + 272 + i;
    g_yhi[off] = __float2half_rn(v);
}

// ---------------------------------------------------------------------------
// GEMM: fp16 tensor-core, single pass (A and W both fp16), BK=64, 3-stage.
//   C[t][d] = sum_c y[c][t] * W[d][c]
// ---------------------------------------------------------------------------
#define BM 128
#define BN 128
#define BK 64
#define ASTRIDE (BM + 8)        // 136 halves
#define BSTRIDE (BK + 8)        // 72 halves
#define ABUF (BK * ASTRIDE)
#define BBUF (BN * BSTRIDE)
#define NSTAGE 3
#define GEMM_SMEM (NSTAGE * (ABUF + BBUF) * 2)   // 107520 bytes

__device__ __forceinline__ void ldmT4(uint32_t* r, uint32_t addr) {
    asm volatile("ldmatrix.sync.aligned.m8n8.x4.trans.shared.b16 {%0,%1,%2,%3},[%4];\n"
                 : "=r"(r[0]), "=r"(r[1]), "=r"(r[2]), "=r"(r[3]) : "r"(addr));
}
__device__ __forceinline__ void ldmN4(uint32_t* r, uint32_t addr) {
    asm volatile("ldmatrix.sync.aligned.m8n8.x4.shared.b16 {%0,%1,%2,%3},[%4];\n"
                 : "=r"(r[0]), "=r"(r[1]), "=r"(r[2]), "=r"(r[3]) : "r"(addr));
}
__device__ __forceinline__ void mma16816(float* c, const uint32_t* a, const uint32_t* b) {
    asm volatile("mma.sync.aligned.m16n8k16.row.col.f32.f16.f16.f32 "
                 "{%0,%1,%2,%3},{%4,%5,%6,%7},{%8,%9},{%0,%1,%2,%3};\n"
                 : "+f"(c[0]), "+f"(c[1]), "+f"(c[2]), "+f"(c[3])
                 : "r"(a[0]), "r"(a[1]), "r"(a[2]), "r"(a[3]), "r"(b[0]), "r"(b[1]));
}

__global__ __launch_bounds__(256, 2) void gemm_fp16(float* __restrict__ out) {
    extern __shared__ __align__(16) unsigned char smem_raw[];
    __half* As = reinterpret_cast<__half*>(smem_raw);
    __half* Bs = As + NSTAGE * ABUF;

    const int tid  = threadIdx.x;
    const int lane = tid & 31;
    const int w    = tid >> 5;
    const int wm   = w & 1;
    const int wn   = w >> 1;

    const int d0 = blockIdx.x * BN;
    const int t0 = blockIdx.y * BM;
    const int z  = blockIdx.z;

    auto issue = [&](int kt, int stg) {
        const int ksrc = kt * BK;
        const __half* Ag = g_yhi + ((size_t)(z * CCH + ksrc)) * TOUT + t0;
        const __half* Bg = g_Whi + (size_t)d0 * CCH + ksrc;
        __half* Asd = As + stg * ABUF;
        __half* Bsd = Bs + stg * BBUF;
        #pragma unroll
        for (int i = 0; i < 4; i++) {
            int cid = tid + 256 * i;
            int ka = cid >> 4, ma = (cid & 15) * 8;
            cp16(&Asd[ka * ASTRIDE + ma], Ag + (size_t)ka * TOUT + ma);
        }
        #pragma unroll
        for (int i = 0; i < 4; i++) {
            int cid = tid + 256 * i;
            int nb = cid >> 3, kb = (cid & 7) * 8;
            cp16(&Bsd[nb * BSTRIDE + kb], Bg + (size_t)nb * CCH + kb);
        }
    };

    const int g  = lane >> 3, r = lane & 7;
    const int ak = ((g & 2) << 2) + r;
    const int amo = (g & 1) << 3;
    const int bn = ((g & 2) << 2) + r;
    const int bko = (g & 1) << 3;

    const uint32_t as0 = smem_u32(As);
    const uint32_t bs0 = smem_u32(Bs);
    uint32_t aAddr[4], bAddr[2];
    #pragma unroll
    for (int mi = 0; mi < 4; mi++)
        aAddr[mi] = as0 + (uint32_t)((ak * ASTRIDE + wm * 64 + mi * 16 + amo) * 2);
    #pragma unroll
    for (int nj = 0; nj < 2; nj++)
        bAddr[nj] = bs0 + (uint32_t)(((wn * 32 + nj * 16 + bn) * BSTRIDE + bko) * 2);

    float acc[4][4][4];
    #pragma unroll
    for (int i = 0; i < 4; i++)
        #pragma unroll
        for (int j = 0; j < 4; j++)
            #pragma unroll
            for (int k = 0; k < 4; k++) acc[i][j][k] = 0.f;

    const int NKT = 6;     // K = 384 / 64

    #pragma unroll
    for (int s = 0; s < NSTAGE - 1; s++) { issue(s, s); cp_commit(); }

    for (int kt = 0; kt < NKT; kt++) {
        cp_wait1();
        __syncthreads();

        const int stg = kt % NSTAGE;
        const uint32_t aob = (uint32_t)(stg * ABUF * 2);
        const uint32_t bob = (uint32_t)(stg * BBUF * 2);
        #pragma unroll
        for (int kh = 0; kh < 4; kh++) {
            uint32_t afr[4][4], bfr[2][4];
            #pragma unroll
            for (int mi = 0; mi < 4; mi++)
                ldmT4(afr[mi], aAddr[mi] + aob + (uint32_t)(kh * 16 * ASTRIDE * 2));
            #pragma unroll
            for (int nj = 0; nj < 2; nj++)
                ldmN4(bfr[nj], bAddr[nj] + bob + (uint32_t)(kh * 32));
            #pragma unroll
            for (int mi = 0; mi < 4; mi++)
                #pragma unroll
                for (int n8 = 0; n8 < 4; n8++)
                    mma16816(acc[mi][n8], afr[mi], &bfr[n8 >> 1][(n8 & 1) * 2]);
        }

        if (kt + NSTAGE - 1 < NKT) issue(kt + NSTAGE - 1, (kt + NSTAGE - 1) % NSTAGE);
        cp_commit();
    }

    // epilogue
    const int cm  = lane >> 2;
    const int cn2 = (lane & 3) << 1;
    #pragma unroll
    for (int mi = 0; mi < 4; mi++) {
        const int t = t0 + wm * 64 + mi * 16 + cm;
        float* orow = out + ((size_t)z * TOUT + t) * CCH + d0 + wn * 32 + cn2;
        #pragma unroll
        for (int n8 = 0; n8 < 4; n8++) {
            float* o1 = orow + n8 * 8;
            *(float2*)o1             = make_float2(acc[mi][n8][0], acc[mi][n8][1]);
            *(float2*)(o1 + 8 * CCH) = make_float2(acc[mi][n8][2], acc[mi][n8][3]);
        }
    }
}

// ---------------------------------------------------------------------------
extern "C" void kernel_launch(void* const* d_in, const int* in_sizes, int n_in,
                              void* d_out, int out_size)
{
    const float* noise = (const float*)d_in[0];   // (768, 65656)
    const float* stdv  = (const float*)d_in[1];   // (384,)
    const float* vt    = (const float*)d_in[2];   // (384, 384)
    const float* kf    = (const float*)d_in[3];   // (257,)

    cudaFuncSetAttribute(gemm_fp16, cudaFuncAttributeMaxDynamicSharedMemorySize, GEMM_SMEM);

    prep_w<<<(CCH * CCH + 255) / 256, 256>>>(vt, stdv);
    prep_tw<<<2, 256>>>(kf);
    conv_kernel<<<dim3(NCHUNK, NROWS / 4), 256>>>(noise);
    fixB<<<NROWS, 384>>>();
    gemm_fp16<<<dim3(CCH / BN, TOUT / BM, 2), 256, GEMM_SMEM>>>((float*)d_out);
}

// round 12
// speedup vs baseline: 5.9834x; 1.3603x over previous
#include <cuda_runtime.h>
#include <cuda_fp16.h>
#include <cstdint>

// Problem constants
#define TPAD  65656      // t_padded = T_SIM + T_KERNEL - 1
#define TOUT  65536      // output time samples
#define CCH   384        // channels
#define NROWS 768        // SIZE * C
#define NB    168        // number of OA blocks
#define HOP   392        // BLOCK - s2 + 1
#define S2    121        // kernel length
#define NFFT  512        // OA block size
#define NCHUNK 24
#define BLKS  7          // blocks per chunk: 24*7 = 168
#define NSTRIP (NCHUNK - 1)   // 23 boundary strips per row

// fp16 filtered signal y[row][t]
__device__ __align__(256) __half g_yhi[(size_t)NROWS * TOUT];
// chunk-boundary strip contributions
__device__ float g_bt[NROWS][NSTRIP][120];    // tail of block 7(s+1)-1
__device__ float g_bh[NROWS][NSTRIP][120];    // head of block 7(s+1)
// Precomputed W[d][c] = std[c]*vt[c][d] in fp16
__device__ __align__(256) __half g_Whi[CCH * CCH];
// FFT tables
__device__ float  g_kss[NFFT];        // symmetric-extended kernel_fft / 512
__device__ float2 g_twl[16 * 32];     // [d][lane] = exp(-2*pi*i*lane*d/512)

// ---------------------------------------------------------------------------
__global__ void prep_w(const float* __restrict__ vt, const float* __restrict__ stdv) {
    int i = blockIdx.x * 256 + threadIdx.x;
    if (i < CCH * CCH) {
        int d = i / CCH, c = i % CCH;
        g_Whi[i] = __float2half_rn(stdv[c] * vt[c * CCH + d]);
    }
}

__global__ void prep_tw(const float* __restrict__ kf) {
    int j = blockIdx.x * 256 + threadIdx.x;
    if (j < NFFT) {
        int kk = (j <= 256) ? j : (NFFT - j);
        g_kss[j] = kf[kk] * (1.0f / (float)NFFT);
        // g_twl[d][lane], j = d*32 + lane
        int d = j >> 5, l = j & 31;
        float s, c;
        sincospif(-(float)(l * d) * (1.0f / 256.0f), &s, &c);
        g_twl[j] = make_float2(c, s);
    }
}

// ---------------------------------------------------------------------------
// Warp-autonomous FFT-512 OA convolution.
// n = 32a + b (a = register slot 0..15, b = lane).
// fwd: FFT16 over a (regs) -> *W512^{bd} -> FFT32 over lanes (shfl, DIF ->
//      bitrev lane order). X[16*bitrev5(lane) + dr4(slot)] per (lane, slot).
// spectrum multiply in that order; inverse mirrors back to natural (a,b).
// ---------------------------------------------------------------------------
__device__ __forceinline__ float2 cadd(float2 a, float2 b) { return make_float2(a.x+b.x, a.y+b.y); }
__device__ __forceinline__ float2 csub(float2 a, float2 b) { return make_float2(a.x-b.x, a.y-b.y); }
__device__ __forceinline__ float2 cmul(float2 a, float2 b) {
    return make_float2(fmaf(a.x, b.x, -a.y * b.y), fmaf(a.x, b.y, a.y * b.x));
}
__device__ __forceinline__ float2 cmulc(float2 a, float2 b) {  // a * conj(b)
    return make_float2(fmaf(a.x, b.x,  a.y * b.y), fmaf(a.y, b.x, -a.x * b.y));
}
__device__ __forceinline__ float2 shflx(float2 v, int m) {
    return make_float2(__shfl_xor_sync(0xffffffffu, v.x, m),
                       __shfl_xor_sync(0xffffffffu, v.y, m));
}
// forward radix-4 butterfly (W4 = -i), in place
__device__ __forceinline__ void fft4f(float2& p0, float2& p1, float2& p2, float2& p3) {
    float2 t0 = cadd(p0, p2), t1 = csub(p0, p2);
    float2 t2 = cadd(p1, p3), t3 = csub(p1, p3);
    p0 = cadd(t0, t2);
    p1 = make_float2(t1.x + t3.y, t1.y - t3.x);   // t1 - i*t3
    p2 = csub(t0, t2);
    p3 = make_float2(t1.x - t3.y, t1.y + t3.x);   // t1 + i*t3
}
// inverse radix-4 butterfly (W4 = +i)
__device__ __forceinline__ void ifft4f(float2& p0, float2& p1, float2& p2, float2& p3) {
    float2 t0 = cadd(p0, p2), t1 = csub(p0, p2);
    float2 t2 = cadd(p1, p3), t3 = csub(p1, p3);
    p0 = cadd(t0, t2);
    p1 = make_float2(t1.x - t3.y, t1.y + t3.x);   // t1 + i*t3
    p2 = csub(t0, t2);
    p3 = make_float2(t1.x + t3.y, t1.y - t3.x);   // t1 - i*t3
}

#define DR4(s) ((((s) & 3) << 2) | ((s) >> 2))

// W16 twiddle constants
#define TC1 0.92387953251128675613f
#define TS1 0.38268343236508977173f
#define TR2 0.70710678118654752440f

// multiply slot s by W16^{(s&3)*(s>>2)} (sign=+1 fwd, -1 inv via conj)
#define TW16(z, s, SGN) do {                                                   \
    const int _e = ((s) & 3) * ((s) >> 2);                                     \
    if (_e == 1)      z[s] = cmul(z[s], make_float2(TC1, (SGN) * -TS1));       \
    else if (_e == 2) z[s] = cmul(z[s], make_float2(TR2, (SGN) * -TR2));       \
    else if (_e == 3) z[s] = cmul(z[s], make_float2(TS1, (SGN) * -TC1));       \
    else if (_e == 4) z[s] = cmul(z[s], make_float2(0.0f, (SGN) * -1.0f));     \
    else if (_e == 6) z[s] = cmul(z[s], make_float2(-TR2, (SGN) * -TR2));      \
    else if (_e == 9) z[s] = cmul(z[s], make_float2(-TC1, (SGN) * TS1));       \
} while (0)

__global__ __launch_bounds__(128) void conv_warp(const float* __restrict__ noise)
{
    __shared__ float2 cbuf[4][2][120];

    const int lane = threadIdx.x & 31;
    const int w    = threadIdx.x >> 5;
    const int ch   = blockIdx.x;                 // 0..23
    const int pr   = blockIdx.y * 4 + w;         // row pair 0..383
    const int row0 = 2 * pr, row1 = row0 + 1;

    const float* n0 = noise + (size_t)row0 * TPAD;
    const float* n1 = noise + (size_t)row1 * TPAD;
    const size_t r0y = (size_t)row0 * TOUT;
    const size_t r1y = (size_t)row1 * TOUT;

    // ---- per-warp setup (lane-dependent constants) ----
    const int rb = __brev((unsigned)lane) >> 27;     // bitrev5(lane)
    float kssr[16];
    #pragma unroll
    for (int s = 0; s < 16; s++) kssr[s] = g_kss[16 * rb + DR4(s)];

    float2 w32, w16, w8;   // forward DIF stage twiddles
    {
        float ss, cc;
        sincospif(-(float)(lane & 15) * (1.0f / 16.0f), &ss, &cc); w32 = make_float2(cc, ss);
        sincospif(-(float)(lane & 7)  * (1.0f / 8.0f),  &ss, &cc); w16 = make_float2(cc, ss);
        sincospif(-(float)(lane & 3)  * (1.0f / 4.0f),  &ss, &cc); w8  = make_float2(cc, ss);
    }

    for (int k = 0; k < BLKS; k++) {
        const int b    = ch * BLKS + k;
        const int base = b * HOP;

        // ---- load: slot a holds (x0[32a+b], x1[32a+b]) ----
        float2 z[16];
        #pragma unroll
        for (int a = 0; a <= 12; a++) {
            int j = 32 * a + lane;
            int p = base + j;
            bool ok = (j < HOP) && (p < TPAD);
            z[a] = ok ? make_float2(__ldg(n0 + p), __ldg(n1 + p))
                      : make_float2(0.f, 0.f);
        }
        z[13] = z[14] = z[15] = make_float2(0.f, 0.f);

        // ---- forward FFT16 over a: inner (stride 4), twiddle, outer (consec) ----
        #pragma unroll
        for (int a0 = 0; a0 < 4; a0++) fft4f(z[a0], z[a0+4], z[a0+8], z[a0+12]);
        #pragma unroll
        for (int s = 0; s < 16; s++) TW16(z, s, 1.0f);
        #pragma unroll
        for (int d0 = 0; d0 < 4; d0++) fft4f(z[4*d0], z[4*d0+1], z[4*d0+2], z[4*d0+3]);
        // slot s now holds Y[b][dr4(s)]

        // ---- twiddle W512^{b*d} ----
        #pragma unroll
        for (int s = 1; s < 16; s++)
            z[s] = cmul(z[s], g_twl[DR4(s) * 32 + lane]);

        // ---- forward FFT32 across lanes (DIF), + spectrum, + inverse FFT32 (DIT) ----
        #pragma unroll
        for (int s = 0; s < 16; s++) {
            float2 v = z[s];
            float2 u, t;
            // fwd h=16
            u = shflx(v, 16);
            t = cmul(csub(u, v), w32);
            v = (lane & 16) ? t : cadd(v, u);
            // fwd h=8
            u = shflx(v, 8);
            t = cmul(csub(u, v), w16);
            v = (lane & 8) ? t : cadd(v, u);
            // fwd h=4
            u = shflx(v, 4);
            t = cmul(csub(u, v), w8);
            v = (lane & 4) ? t : cadd(v, u);
            // fwd h=2, tw = -i for odd lane
            u = shflx(v, 2);
            t = csub(u, v);
            if (lane & 1) t = make_float2(t.y, -t.x);
            v = (lane & 2) ? t : cadd(v, u);
            // fwd h=1
            u = shflx(v, 1);
            v = (lane & 1) ? csub(u, v) : cadd(v, u);

            // spectrum multiply (bitrev lane order, dr4 slot order)
            v.x *= kssr[s]; v.y *= kssr[s];

            // inv h=1
            u = shflx(v, 1);
            v = (lane & 1) ? csub(u, v) : cadd(v, u);
            // inv h=2, pre-twiddle +i on lanes with (lane&3)==3
            t = ((lane & 3) == 3) ? make_float2(-v.y, v.x) : v;
            u = shflx(t, 2);
            v = (lane & 2) ? csub(u, t) : cadd(t, u);
            // inv h=4
            t = (lane & 4) ? cmulc(v, w8) : v;
            u = shflx(t, 4);
            v = (lane & 4) ? csub(u, t) : cadd(t, u);
            // inv h=8
            t = (lane & 8) ? cmulc(v, w16) : v;
            u = shflx(t, 8);
            v = (lane & 8) ? csub(u, t) : cadd(t, u);
            // inv h=16
            t = (lane & 16) ? cmulc(v, w32) : v;
            u = shflx(t, 16);
            v = (lane & 16) ? csub(u, t) : cadd(t, u);

            z[s] = v;
        }

        // ---- conj twiddle W512^{-b*d} ----
        #pragma unroll
        for (int s = 1; s < 16; s++)
            z[s] = cmulc(z[s], g_twl[DR4(s) * 32 + lane]);

        // ---- inverse FFT16 over d: inner (consec), conj twiddle, outer (stride 4) ----
        #pragma unroll
        for (int d0 = 0; d0 < 4; d0++) ifft4f(z[4*d0], z[4*d0+1], z[4*d0+2], z[4*d0+3]);
        #pragma unroll
        for (int s = 0; s < 16; s++) TW16(z, s, -1.0f);
        #pragma unroll
        for (int a0 = 0; a0 < 4; a0++) ifft4f(z[a0], z[a0+4], z[a0+8], z[a0+12]);
        // slot a now holds y sample j = 32a + lane (both rows)

        // ---- routed writeout with per-warp carry ----
        float2*       cw = cbuf[w][k & 1];
        const float2* cr = cbuf[w][(k & 1) ^ 1];

        // heads: slots 0..3 (j < 120)
        if (k == 0) {
            if (ch > 0) {
                #pragma unroll
                for (int a = 0; a < 4; a++) {
                    int j = 32 * a + lane;
                    if (j < S2 - 1) {
                        g_bh[row0][ch - 1][j] = z[a].x;
                        g_bh[row1][ch - 1][j] = z[a].y;
                    }
                }
            }
        } else {
            #pragma unroll
            for (int a = 0; a < 4; a++) {
                int j = 32 * a + lane;
                if (j < S2 - 1) {
                    float2 cv = cr[j];
                    int t = base + j - (S2 - 1);
                    g_yhi[r0y + t] = __float2half_rn(z[a].x + cv.x);
                    g_yhi[r1y + t] = __float2half_rn(z[a].y + cv.y);
                }
            }
        }
        // exclusive region: slots 3..12 (120 <= j < 392)
        #pragma unroll
        for (int a = 3; a <= 12; a++) {
            int j = 32 * a + lane;
            if (j >= S2 - 1 && j < HOP) {
                int t = base + j - (S2 - 1);
                if (t < TOUT) {
                    g_yhi[r0y + t] = __float2half_rn(z[a].x);
                    g_yhi[r1y + t] = __float2half_rn(z[a].y);
                }
            }
        }
        // tails: slots 12..15 (j >= 392)
        #pragma unroll
        for (int a = 12; a < 16; a++) {
            int j = 32 * a + lane;
            if (j >= HOP) {
                int idx = j - HOP;
                if (k < BLKS - 1) {
                    cw[idx] = z[a];
                } else if (ch < NCHUNK - 1) {
                    g_bt[row0][ch][idx] = z[a].x;
                    g_bt[row1][ch][idx] = z[a].y;
                }
            }
        }
        __syncwarp();
    }
}

// ---------------------------------------------------------------------------
// fixB: the 23 chunk-boundary strips per row (b = 7(s+1)-1).
// ---------------------------------------------------------------------------
__global__ __launch_bounds__(256) void fixB() {
    const int row = blockIdx.x;
    for (int idx = threadIdx.x; idx < NSTRIP * 120; idx += 256) {
        int sb = idx / 120;
        int i  = idx - sb * 120;
        int b  = BLKS * (sb + 1) - 1;
        float v = g_bt[row][sb][i] + g_bh[row][sb][i];
        size_t off = (size_t)row * TOUT + b * HOP + 272 + i;
        g_yhi[off] = __float2half_rn(v);
    }
}

// ---------------------------------------------------------------------------
// GEMM: fp16 tensor-core, single pass, BK=64, 3-stage cp.async (unchanged).
//   C[t][d] = sum_c y[c][t] * W[d][c]
// ---------------------------------------------------------------------------
#define BM 128
#define BN 128
#define BK 64
#define ASTRIDE (BM + 8)
#define BSTRIDE (BK + 8)
#define ABUF (BK * ASTRIDE)
#define BBUF (BN * BSTRIDE)
#define NSTAGE 3
#define GEMM_SMEM (NSTAGE * (ABUF + BBUF) * 2)   // 107520 bytes

__device__ __forceinline__ uint32_t smem_u32(const void* p) {
    return (uint32_t)__cvta_generic_to_shared(p);
}
__device__ __forceinline__ void cp16(void* dst, const void* src) {
    asm volatile("cp.async.ca.shared.global [%0], [%1], 16;\n"
                 :: "r"(smem_u32(dst)), "l"(src));
}
__device__ __forceinline__ void cp_commit() { asm volatile("cp.async.commit_group;\n"); }
__device__ __forceinline__ void cp_wait1()  { asm volatile("cp.async.wait_group 1;\n"); }

__device__ __forceinline__ void ldmT4(uint32_t* r, uint32_t addr) {
    asm volatile("ldmatrix.sync.aligned.m8n8.x4.trans.shared.b16 {%0,%1,%2,%3},[%4];\n"
                 : "=r"(r[0]), "=r"(r[1]), "=r"(r[2]), "=r"(r[3]) : "r"(addr));
}
__device__ __forceinline__ void ldmN4(uint32_t* r, uint32_t addr) {
    asm volatile("ldmatrix.sync.aligned.m8n8.x4.shared.b16 {%0,%1,%2,%3},[%4];\n"
                 : "=r"(r[0]), "=r"(r[1]), "=r"(r[2]), "=r"(r[3]) : "r"(addr));
}
__device__ __forceinline__ void mma16816(float* c, const uint32_t* a, const uint32_t* b) {
    asm volatile("mma.sync.aligned.m16n8k16.row.col.f32.f16.f16.f32 "
                 "{%0,%1,%2,%3},{%4,%5,%6,%7},{%8,%9},{%0,%1,%2,%3};\n"
                 : "+f"(c[0]), "+f"(c[1]), "+f"(c[2]), "+f"(c[3])
                 : "r"(a[0]), "r"(a[1]), "r"(a[2]), "r"(a[3]), "r"(b[0]), "r"(b[1]));
}

__global__ __launch_bounds__(256, 2) void gemm_fp16(float* __restrict__ out) {
    extern __shared__ __align__(16) unsigned char smem_raw[];
    __half* As = reinterpret_cast<__half*>(smem_raw);
    __half* Bs = As + NSTAGE * ABUF;

    const int tid  = threadIdx.x;
    const int lane = tid & 31;
    const int w    = tid >> 5;
    const int wm   = w & 1;
    const int wn   = w >> 1;

    const int d0 = blockIdx.x * BN;
    const int t0 = blockIdx.y * BM;
    const int z  = blockIdx.z;

    auto issue = [&](int kt, int stg) {
        const int ksrc = kt * BK;
        const __half* Ag = g_yhi + ((size_t)(z * CCH + ksrc)) * TOUT + t0;
        const __half* Bg = g_Whi + (size_t)d0 * CCH + ksrc;
        __half* Asd = As + stg * ABUF;
        __half* Bsd = Bs + stg * BBUF;
        #pragma unroll
        for (int i = 0; i < 4; i++) {
            int cid = tid + 256 * i;
            int ka = cid >> 4, ma = (cid & 15) * 8;
            cp16(&Asd[ka * ASTRIDE + ma], Ag + (size_t)ka * TOUT + ma);
        }
        #pragma unroll
        for (int i = 0; i < 4; i++) {
            int cid = tid + 256 * i;
            int nb = cid >> 3, kb = (cid & 7) * 8;
            cp16(&Bsd[nb * BSTRIDE + kb], Bg + (size_t)nb * CCH + kb);
        }
    };

    const int g  = lane >> 3, r = lane & 7;
    const int ak = ((g & 2) << 2) + r;
    const int amo = (g & 1) << 3;
    const int bn = ((g & 2) << 2) + r;
    const int bko = (g & 1) << 3;

    const uint32_t as0 = smem_u32(As);
    const uint32_t bs0 = smem_u32(Bs);
    uint32_t aAddr[4], bAddr[2];
    #pragma unroll
    for (int mi = 0; mi < 4; mi++)
        aAddr[mi] = as0 + (uint32_t)((ak * ASTRIDE + wm * 64 + mi * 16 + amo) * 2);
    #pragma unroll
    for (int nj = 0; nj < 2; nj++)
        bAddr[nj] = bs0 + (uint32_t)(((wn * 32 + nj * 16 + bn) * BSTRIDE + bko) * 2);

    float acc[4][4][4];
    #pragma unroll
    for (int i = 0; i < 4; i++)
        #pragma unroll
        for (int j = 0; j < 4; j++)
            #pragma unroll
            for (int k = 0; k < 4; k++) acc[i][j][k] = 0.f;

    const int NKT = 6;

    #pragma unroll
    for (int s = 0; s < NSTAGE - 1; s++) { issue(s, s); cp_commit(); }

    for (int kt = 0; kt < NKT; kt++) {
        cp_wait1();
        __syncthreads();

        const int stg = kt % NSTAGE;
        const uint32_t aob = (uint32_t)(stg * ABUF * 2);
        const uint32_t bob = (uint32_t)(stg * BBUF * 2);
        #pragma unroll
        for (int kh = 0; kh < 4; kh++) {
            uint32_t afr[4][4], bfr[2][4];
            #pragma unroll
            for (int mi = 0; mi < 4; mi++)
                ldmT4(afr[mi], aAddr[mi] + aob + (uint32_t)(kh * 16 * ASTRIDE * 2));
            #pragma unroll
            for (int nj = 0; nj < 2; nj++)
                ldmN4(bfr[nj], bAddr[nj] + bob + (uint32_t)(kh * 32));
            #pragma unroll
            for (int mi = 0; mi < 4; mi++)
                #pragma unroll
                for (int n8 = 0; n8 < 4; n8++)
                    mma16816(acc[mi][n8], afr[mi], &bfr[n8 >> 1][(n8 & 1) * 2]);
        }

        if (kt + NSTAGE - 1 < NKT) issue(kt + NSTAGE - 1, (kt + NSTAGE - 1) % NSTAGE);
        cp_commit();
    }

    // epilogue
    const int cm  = lane >> 2;
    const int cn2 = (lane & 3) << 1;
    #pragma unroll
    for (int mi = 0; mi < 4; mi++) {
        const int t = t0 + wm * 64 + mi * 16 + cm;
        float* orow = out + ((size_t)z * TOUT + t) * CCH + d0 + wn * 32 + cn2;
        #pragma unroll
        for (int n8 = 0; n8 < 4; n8++) {
            float* o1 = orow + n8 * 8;
            *(float2*)o1             = make_float2(acc[mi][n8][0], acc[mi][n8][1]);
            *(float2*)(o1 + 8 * CCH) = make_float2(acc[mi][n8][2], acc[mi][n8][3]);
        }
    }
}

// ---------------------------------------------------------------------------
extern "C" void kernel_launch(void* const* d_in, const int* in_sizes, int n_in,
                              void* d_out, int out_size)
{
    const float* noise = (const float*)d_in[0];   // (768, 65656)
    const float* stdv  = (const float*)d_in[1];   // (384,)
    const float* vt    = (const float*)d_in[2];   // (384, 384)
    const float* kf    = (const float*)d_in[3];   // (257,)

    cudaFuncSetAttribute(gemm_fp16, cudaFuncAttributeMaxDynamicSharedMemorySize, GEMM_SMEM);

    prep_w<<<(CCH * CCH + 255) / 256, 256>>>(vt, stdv);
    prep_tw<<<2, 256>>>(kf);
    conv_warp<<<dim3(NCHUNK, 96), 128>>>(noise);
    fixB<<<NROWS, 256>>>();
    gemm_fp16<<<dim3(CCH / BN, TOUT / BM, 2), 256, GEMM_SMEM>>>((float*)d_out);
}